// round 6
// baseline (speedup 1.0000x reference)
#include <cuda_runtime.h>
#include <cuda_bf16.h>
#include <cstdint>

#define NN 768
#define PP (NN*NN)

__device__ __align__(256) __nv_bfloat16 g_left [(size_t)128 * PP];  // [d][i*N+k]
__device__ __align__(256) __nv_bfloat16 g_right[(size_t)128 * PP];  // [d][j*N+k]
__device__ __align__(256) __nv_bfloat16 g_pair [(size_t)128 * PP];  // [d][i*N+j]
__device__ __align__(256) float         g_ogate[(size_t)PP  * 128]; // [p][h]

// ---------------- Stage A: LN + 5 projections + gating (fp32) ----------------
#define SA_SMEM ((64*128 + 2*64*68 + 64*65)*4)

__global__ __launch_bounds__(256, 2) void stage_a(
    const float* __restrict__ x,   const float* __restrict__ mask,
    const float* __restrict__ nw,  const float* __restrict__ nb,
    const float* __restrict__ wl,  const float* __restrict__ wr,
    const float* __restrict__ wlg, const float* __restrict__ wrg,
    const float* __restrict__ wog)
{
    extern __shared__ float sm[];
    float* s_xn = sm;                            // [64][128]
    float* s_w  = sm + 64*128;                   // [2][64][68]
    float* s_og = s_w + 2*64*68;                 // [64][65] f32 staging
    __nv_bfloat16* s_st = (__nv_bfloat16*)s_og;  // [64][66] bf16 staging (alias)

    const int tid = threadIdx.x, lane = tid & 31, warp = tid >> 5;
    const int tx = tid & 15, ty = tid >> 4;
    const int bi = blockIdx.x / 12, k0 = (blockIdx.x % 12) * 64;
    const size_t pbase = (size_t)bi * NN + k0;

    { // load x tile [64 pos][128 c]
        const float4* xg = (const float4*)(x + pbase * 128);
        float4* s4 = (float4*)s_xn;
        #pragma unroll
        for (int r = 0; r < 8; r++) s4[tid + 256*r] = xg[tid + 256*r];
    }
    __syncthreads();

    #pragma unroll 1
    for (int pp = 0; pp < 8; pp++) { // LayerNorm, warp per position
        int pos = warp*8 + pp;
        float4 v = ((const float4*)(s_xn + pos*128))[lane];
        float s  = v.x+v.y+v.z+v.w;
        float sq = v.x*v.x+v.y*v.y+v.z*v.z+v.w*v.w;
        #pragma unroll
        for (int o = 16; o; o >>= 1) {
            s  += __shfl_xor_sync(~0u, s,  o);
            sq += __shfl_xor_sync(~0u, sq, o);
        }
        float mu = s*(1.f/128.f), var = sq*(1.f/128.f) - mu*mu;
        float rstd = rsqrtf(var + 1e-5f);
        float4 w4 = ((const float4*)nw)[lane], b4 = ((const float4*)nb)[lane];
        v.x=(v.x-mu)*rstd*w4.x+b4.x; v.y=(v.y-mu)*rstd*w4.y+b4.y;
        v.z=(v.z-mu)*rstd*w4.z+b4.z; v.w=(v.w-mu)*rstd*w4.w+b4.w;
        ((float4*)(s_xn + pos*128))[lane] = v;
    }
    __syncthreads();

    float mreg[4];
    #pragma unroll
    for (int a = 0; a < 4; a++) mreg[a] = mask[pbase + ty + 16*a];

    #pragma unroll 1
    for (int mat = 0; mat < 3; mat++) {
        const float* WA = (mat==0) ? wl  : (mat==1) ? wr  : wog;
        const float* WB = (mat==0) ? wlg : (mat==1) ? wrg : wog;
        const bool dual = (mat < 2);

        #pragma unroll 1
        for (int hb = 0; hb < 2; hb++) {
            const int hbase = hb * 64;
            float accA[4][4] = {}, accB[4][4] = {};

            #pragma unroll 1
            for (int ch = 0; ch < 2; ch++) {
                const int c0 = ch * 64;
                __syncthreads();
                #pragma unroll
                for (int q = 0; q < 4; q++) {
                    int idx = tid + 256*q, row = idx >> 4, c4 = (idx & 15) << 2;
                    *(float4*)(s_w + row*68 + c4) =
                        *(const float4*)(WA + (size_t)(hbase+row)*128 + c0 + c4);
                    if (dual)
                        *(float4*)(s_w + 64*68 + row*68 + c4) =
                            *(const float4*)(WB + (size_t)(hbase+row)*128 + c0 + c4);
                }
                __syncthreads();

                #pragma unroll 4
                for (int c = 0; c < 64; c += 4) {
                    float4 av[4], wa4[4], wb4[4];
                    #pragma unroll
                    for (int a = 0; a < 4; a++)
                        av[a] = *(const float4*)(s_xn + (ty+16*a)*128 + c0 + c);
                    #pragma unroll
                    for (int b = 0; b < 4; b++) {
                        wa4[b] = *(const float4*)(s_w + (tx+16*b)*68 + c);
                        if (dual) wb4[b] = *(const float4*)(s_w + 64*68 + (tx+16*b)*68 + c);
                    }
                    #pragma unroll
                    for (int a = 0; a < 4; a++)
                        #pragma unroll
                        for (int b = 0; b < 4; b++) {
                            accA[a][b] += av[a].x*wa4[b].x + av[a].y*wa4[b].y
                                        + av[a].z*wa4[b].z + av[a].w*wa4[b].w;
                            if (dual)
                                accB[a][b] += av[a].x*wb4[b].x + av[a].y*wb4[b].y
                                            + av[a].z*wb4[b].z + av[a].w*wb4[b].w;
                        }
                }
            }
            __syncthreads();
            if (mat < 2) {
                __nv_bfloat16* dst = (mat==0) ? g_left : g_right;
                #pragma unroll
                for (int a = 0; a < 4; a++)
                    #pragma unroll
                    for (int b = 0; b < 4; b++) {
                        float g = 1.f/(1.f + __expf(-accB[a][b]));
                        s_st[(tx+16*b)*66 + (ty+16*a)] =
                            __float2bfloat16(accA[a][b] * mreg[a] * g);
                    }
                __syncthreads();
                #pragma unroll
                for (int q = 0; q < 16; q++) {
                    int idx = tid + 256*q, hh = idx >> 6, pos = idx & 63;
                    dst[(size_t)(hbase+hh)*PP + pbase + pos] = s_st[hh*66 + pos];
                }
            } else {
                #pragma unroll
                for (int a = 0; a < 4; a++)
                    #pragma unroll
                    for (int b = 0; b < 4; b++)
                        s_og[(ty+16*a)*65 + (tx+16*b)] =
                            1.f/(1.f + __expf(-accA[a][b]));
                __syncthreads();
                #pragma unroll
                for (int q = 0; q < 16; q++) {
                    int idx = tid + 256*q, pos = idx >> 6, hh = idx & 63;
                    g_ogate[(pbase+pos)*128 + hbase + hh] = s_og[pos*65 + hh];
                }
            }
            __syncthreads();
        }
    }
}

// ---------------- Stage B: per-channel bf16 einsum (mma.sync) ----------------
__device__ __forceinline__ void cpa16(void* dst, const void* src) {
    unsigned u = (unsigned)__cvta_generic_to_shared(dst);
    asm volatile("cp.async.cg.shared.global [%0], [%1], 16;\n" :: "r"(u), "l"(src) : "memory");
}
__device__ __forceinline__ void mma16816(float* c, const uint32_t* a, const uint32_t* b) {
    asm volatile("mma.sync.aligned.m16n8k16.row.col.f32.bf16.bf16.f32 "
                 "{%0,%1,%2,%3}, {%4,%5,%6,%7}, {%8,%9}, {%0,%1,%2,%3};\n"
                 : "+f"(c[0]), "+f"(c[1]), "+f"(c[2]), "+f"(c[3])
                 : "r"(a[0]), "r"(a[1]), "r"(a[2]), "r"(a[3]), "r"(b[0]), "r"(b[1]));
}
__device__ __forceinline__ void sb_issue(const __nv_bfloat16* gA, const __nv_bfloat16* gB,
                                         __nv_bfloat16* sA, __nv_bfloat16* sB, int tid, int k0) {
    #pragma unroll
    for (int q = 0; q < 2; q++) {
        int idx = tid + 256*q, row = idx >> 2, seg = (idx & 3) << 3;
        cpa16(sA + row*40 + seg, gA + (size_t)row*NN + k0 + seg);
        cpa16(sB + row*40 + seg, gB + (size_t)row*NN + k0 + seg);
    }
    asm volatile("cp.async.commit_group;\n" ::: "memory");
}

__global__ __launch_bounds__(256, 2) void stage_b() {
    __shared__ __align__(16) __nv_bfloat16 smb[4*128*40];
    __nv_bfloat16* sA = smb;             // [2 buf][128][40]
    __nv_bfloat16* sB = smb + 2*128*40;

    const int tid = threadIdx.x, lane = tid & 31, warp = tid >> 5;
    const int wm = warp & 1, wn = warp >> 1;
    const int d = blockIdx.y, ti = blockIdx.x / 6, tj = blockIdx.x % 6;
    const __nv_bfloat16* gA = g_left  + (size_t)d*PP + (size_t)(ti*128)*NN;
    const __nv_bfloat16* gB = g_right + (size_t)d*PP + (size_t)(tj*128)*NN;

    float c[4][4][4] = {};
    sb_issue(gA, gB, sA, sB, tid, 0);

    #pragma unroll 1
    for (int kt = 0; kt < 24; kt++) {
        int buf = kt & 1;
        if (kt < 23) {
            sb_issue(gA, gB, sA + (buf^1)*5120, sB + (buf^1)*5120, tid, (kt+1)*32);
            asm volatile("cp.async.wait_group 1;\n" ::: "memory");
        } else {
            asm volatile("cp.async.wait_group 0;\n" ::: "memory");
        }
        __syncthreads();
        const uint32_t* At = (const uint32_t*)(sA + buf*5120);
        const uint32_t* Bt = (const uint32_t*)(sB + buf*5120);
        #pragma unroll
        for (int kk = 0; kk < 2; kk++) {
            uint32_t a[4][4], b[4][2];
            const int kw = kk*8 + (lane & 3);
            #pragma unroll
            for (int fm = 0; fm < 4; fm++) {
                int r = wm*64 + fm*16 + (lane >> 2);
                a[fm][0] = At[r*20+kw];   a[fm][1] = At[(r+8)*20+kw];
                a[fm][2] = At[r*20+kw+4]; a[fm][3] = At[(r+8)*20+kw+4];
            }
            #pragma unroll
            for (int fn = 0; fn < 4; fn++) {
                int n = wn*32 + fn*8 + (lane >> 2);
                b[fn][0] = Bt[n*20+kw]; b[fn][1] = Bt[n*20+kw+4];
            }
            #pragma unroll
            for (int fm = 0; fm < 4; fm++)
                #pragma unroll
                for (int fn = 0; fn < 4; fn++) mma16816(c[fm][fn], a[fm], b[fn]);
        }
        __syncthreads();
    }

    __nv_bfloat16* gO = g_pair + (size_t)d*PP;
    #pragma unroll
    for (int fm = 0; fm < 4; fm++)
        #pragma unroll
        for (int fn = 0; fn < 4; fn++) {
            int r0 = ti*128 + wm*64 + fm*16 + (lane >> 2);
            int cc = tj*128 + wn*32 + fn*8 + (lane & 3)*2;
            *(__nv_bfloat162*)(gO + (size_t)r0*NN + cc) =
                __float22bfloat162_rn(make_float2(c[fm][fn][0], c[fm][fn][1]));
            *(__nv_bfloat162*)(gO + (size_t)(r0+8)*NN + cc) =
                __float22bfloat162_rn(make_float2(c[fm][fn][2], c[fm][fn][3]));
        }
}

// ------------- Stage C: LN over H + out_gate + final projection -------------
#define SC_SMEM (2*128*133*4)

__global__ __launch_bounds__(256) void stage_c(
    const float* __restrict__ onw, const float* __restrict__ onb,
    const float* __restrict__ wout, float* __restrict__ out)
{
    extern __shared__ float smc[];
    float* s_v = smc;                           // [128 pos][133]
    float* s_w = smc + 128*133;                 // [128 dout][133]
    __nv_bfloat16* s_t = (__nv_bfloat16*)s_w;   // [128 d][132] alias (dead before s_w fill)

    const int tid = threadIdx.x, lane = tid & 31, warp = tid >> 5;
    const int tx = tid & 15, ty = tid >> 4;
    const size_t p0 = (size_t)blockIdx.x * 128;

    #pragma unroll
    for (int q = 0; q < 16; q++) { // pair tile [128 d][128 pos], uint2 = 4 bf16 (8B)
        int idx = tid + 256*q, dd = idx >> 5, seg = (idx & 31) << 2;
        *(uint2*)(s_t + dd*132 + seg) = *(const uint2*)(g_pair + (size_t)dd*PP + p0 + seg);
    }
    __syncthreads();

    float lw[4], lb[4];
    #pragma unroll
    for (int q = 0; q < 4; q++) { lw[q] = onw[lane+32*q]; lb[q] = onb[lane+32*q]; }

    #pragma unroll 1
    for (int pp = 0; pp < 16; pp++) { // LN over d, warp per position
        int pos = warp*16 + pp;
        float t[4];
        #pragma unroll
        for (int q = 0; q < 4; q++) t[q] = __bfloat162float(s_t[(lane+32*q)*132 + pos]);
        float s = t[0]+t[1]+t[2]+t[3];
        float sq = t[0]*t[0]+t[1]*t[1]+t[2]*t[2]+t[3]*t[3];
        #pragma unroll
        for (int o = 16; o; o >>= 1) {
            s  += __shfl_xor_sync(~0u, s,  o);
            sq += __shfl_xor_sync(~0u, sq, o);
        }
        float mu = s*(1.f/128.f), var = sq*(1.f/128.f) - mu*mu;
        float rstd = rsqrtf(var + 1e-5f);
        #pragma unroll
        for (int q = 0; q < 4; q++) {
            float v = (t[q]-mu)*rstd*lw[q] + lb[q];
            v *= g_ogate[(p0+pos)*128 + lane + 32*q];
            s_v[pos*133 + lane + 32*q] = v;
        }
    }
    __syncthreads();

    #pragma unroll
    for (int q = 0; q < 64; q++) { // w_out [128][128] scalar fill (overwrites s_t)
        int idx = tid + 256*q, row = idx >> 7, cc = idx & 127;
        s_w[row*133 + cc] = wout[(size_t)row*128 + cc];
    }
    __syncthreads();

    float acc[8][8] = {};
    #pragma unroll 2
    for (int c = 0; c < 128; c++) {
        float av[8], wv[8];
        #pragma unroll
        for (int a = 0; a < 8; a++) av[a] = s_v[(ty+16*a)*133 + c];
        #pragma unroll
        for (int b = 0; b < 8; b++) wv[b] = s_w[(tx+16*b)*133 + c];
        #pragma unroll
        for (int a = 0; a < 8; a++)
            #pragma unroll
            for (int b = 0; b < 8; b++) acc[a][b] += av[a]*wv[b];
    }
    #pragma unroll
    for (int a = 0; a < 8; a++)
        #pragma unroll
        for (int b = 0; b < 8; b++)
            out[(p0 + ty + 16*a)*128 + tx + 16*b] = acc[a][b];
}

// -----------------------------------------------------------------------------
extern "C" void kernel_launch(void* const* d_in, const int* in_sizes, int n_in,
                              void* d_out, int out_size) {
    (void)in_sizes; (void)n_in; (void)out_size;
    const float* x    = (const float*)d_in[0];
    const float* mask = (const float*)d_in[1];
    const float* nw   = (const float*)d_in[2];
    const float* nb   = (const float*)d_in[3];
    const float* wl   = (const float*)d_in[4];
    const float* wr   = (const float*)d_in[5];
    const float* wlg  = (const float*)d_in[6];
    const float* wrg  = (const float*)d_in[7];
    const float* wog  = (const float*)d_in[8];
    const float* onw  = (const float*)d_in[9];
    const float* onb  = (const float*)d_in[10];
    const float* wout = (const float*)d_in[11];
    float* out = (float*)d_out;

    cudaFuncSetAttribute(stage_a, cudaFuncAttributeMaxDynamicSharedMemorySize, SA_SMEM);
    cudaFuncSetAttribute(stage_c, cudaFuncAttributeMaxDynamicSharedMemorySize, SC_SMEM);

    stage_a<<<768*12, 256, SA_SMEM>>>(x, mask, nw, nb, wl, wr, wlg, wrg, wog);
    stage_b<<<dim3(36, 128), 256>>>();
    stage_c<<<PP/128, 256, SC_SMEM>>>(onw, onb, wout, out);
}

// round 7
// speedup vs baseline: 1.4753x; 1.4753x over previous
#include <cuda_runtime.h>
#include <cuda_bf16.h>
#include <cstdint>

#define NN 768
#define PP (NN*NN)

__device__ __align__(256) __nv_bfloat16 g_xhi [(size_t)PP  * 128]; // [p][d]
__device__ __align__(256) __nv_bfloat16 g_xlo [(size_t)PP  * 128]; // [p][d]
__device__ __align__(256) __nv_bfloat16 g_left [(size_t)128 * PP]; // [h][i*N+k]
__device__ __align__(256) __nv_bfloat16 g_right[(size_t)128 * PP]; // [h][j*N+k]
__device__ __align__(256) __nv_bfloat16 g_pair [(size_t)128 * PP]; // [d][i*N+j]
__device__ __align__(256) float         g_ogate[(size_t)PP  * 128]; // [p][h]

// ---------------- Stage LN: LayerNorm + hi/lo bf16 split ----------------
__global__ __launch_bounds__(256) void stage_ln(
    const float* __restrict__ x, const float* __restrict__ nw,
    const float* __restrict__ nb)
{
    const int lane = threadIdx.x & 31, warp = threadIdx.x >> 5;
    const size_t pbase = (size_t)blockIdx.x * 64;
    float4 w4 = ((const float4*)nw)[lane], b4 = ((const float4*)nb)[lane];

    #pragma unroll 1
    for (int pp = 0; pp < 8; pp++) {
        size_t gpos = pbase + warp*8 + pp;
        float4 v = ((const float4*)(x + gpos*128))[lane];
        float s  = v.x+v.y+v.z+v.w;
        float sq = v.x*v.x+v.y*v.y+v.z*v.z+v.w*v.w;
        #pragma unroll
        for (int o = 16; o; o >>= 1) {
            s  += __shfl_xor_sync(~0u, s,  o);
            sq += __shfl_xor_sync(~0u, sq, o);
        }
        float mu = s*(1.f/128.f), var = sq*(1.f/128.f) - mu*mu;
        float rstd = rsqrtf(var + 1e-5f);
        v.x=(v.x-mu)*rstd*w4.x+b4.x; v.y=(v.y-mu)*rstd*w4.y+b4.y;
        v.z=(v.z-mu)*rstd*w4.z+b4.z; v.w=(v.w-mu)*rstd*w4.w+b4.w;
        __nv_bfloat16 hx=__float2bfloat16_rn(v.x), hy=__float2bfloat16_rn(v.y);
        __nv_bfloat16 hz=__float2bfloat16_rn(v.z), hw=__float2bfloat16_rn(v.w);
        __nv_bfloat162 h01; h01.x=hx; h01.y=hy;
        __nv_bfloat162 h23; h23.x=hz; h23.y=hw;
        __nv_bfloat162 l01 = __floats2bfloat162_rn(v.x-__bfloat162float(hx), v.y-__bfloat162float(hy));
        __nv_bfloat162 l23 = __floats2bfloat162_rn(v.z-__bfloat162float(hz), v.w-__bfloat162float(hw));
        *(__nv_bfloat162*)(g_xhi + gpos*128 + lane*4)     = h01;
        *(__nv_bfloat162*)(g_xhi + gpos*128 + lane*4 + 2) = h23;
        *(__nv_bfloat162*)(g_xlo + gpos*128 + lane*4)     = l01;
        *(__nv_bfloat162*)(g_xlo + gpos*128 + lane*4 + 2) = l23;
    }
}

// ---------------- mma helpers ----------------
__device__ __forceinline__ void mma16816(float* c, const uint32_t* a, const uint32_t* b) {
    asm volatile("mma.sync.aligned.m16n8k16.row.col.f32.bf16.bf16.f32 "
                 "{%0,%1,%2,%3}, {%4,%5,%6,%7}, {%8,%9}, {%0,%1,%2,%3};\n"
                 : "+f"(c[0]), "+f"(c[1]), "+f"(c[2]), "+f"(c[3])
                 : "r"(a[0]), "r"(a[1]), "r"(a[2]), "r"(a[3]), "r"(b[0]), "r"(b[1]));
}

// 128x128x128 split-bf16 GEMM tile: acc += X * W^T, 4 hi/lo cross passes.
__device__ __forceinline__ void gemm_tile(
    float (&acc)[2][8][4],
    const __nv_bfloat16* sXh, const __nv_bfloat16* sXl,
    const __nv_bfloat16* sWh, const __nv_bfloat16* sWl,
    int lane, int wm, int wn)
{
    #pragma unroll 1
    for (int pass = 0; pass < 4; pass++) {
        const uint32_t* X = (const uint32_t*)((pass & 2) ? sXl : sXh);
        const uint32_t* W = (const uint32_t*)((pass & 1) ? sWl : sWh);
        #pragma unroll
        for (int ks = 0; ks < 8; ks++) {
            const int kw = ks*8 + (lane & 3);
            uint32_t a[2][4], b[8][2];
            #pragma unroll
            for (int mf = 0; mf < 2; mf++) {
                int r = wm*32 + mf*16 + (lane >> 2);
                a[mf][0]=X[r*68+kw];   a[mf][1]=X[(r+8)*68+kw];
                a[mf][2]=X[r*68+kw+4]; a[mf][3]=X[(r+8)*68+kw+4];
            }
            #pragma unroll
            for (int nf = 0; nf < 8; nf++) {
                int n = wn*64 + nf*8 + (lane >> 2);
                b[nf][0]=W[n*68+kw]; b[nf][1]=W[n*68+kw+4];
            }
            #pragma unroll
            for (int mf = 0; mf < 2; mf++)
                #pragma unroll
                for (int nf = 0; nf < 8; nf++)
                    mma16816(acc[mf][nf], a[mf], b[nf]);
        }
    }
}

// ---------------- Stage A (mma): projections + gating ----------------
#define AM_SMEM (104448*2)

__global__ __launch_bounds__(256, 1) void stage_amm(
    const float* __restrict__ mask,
    const float* __restrict__ wl, const float* __restrict__ wr,
    const float* __restrict__ wlg, const float* __restrict__ wrg,
    const float* __restrict__ wog)
{
    extern __shared__ __nv_bfloat16 smem[];
    __nv_bfloat16* sXh  = smem;            // [128][136]
    __nv_bfloat16* sXl  = smem + 17408;
    __nv_bfloat16* sWAh = smem + 34816;
    __nv_bfloat16* sWAl = smem + 52224;
    __nv_bfloat16* sWBh = smem + 69632;
    __nv_bfloat16* sWBl = smem + 87040;

    const int tid = threadIdx.x, lane = tid & 31, warp = tid >> 5;
    const int wm = warp & 3, wn = warp >> 2;
    const int mat = blockIdx.y;
    const bool dual = (mat < 2);
    const size_t pbase = (size_t)blockIdx.x * 128;
    const float* WA = (mat==0) ? wl : (mat==1) ? wr : wog;
    const float* WB = (mat==0) ? wlg : wrg;

    #pragma unroll
    for (int q = 0; q < 8; q++) { // X tiles (hi/lo)
        int idx = tid + 256*q, r = idx >> 4, seg = (idx & 15) << 3;
        *(uint4*)(sXh + r*136 + seg) = *(const uint4*)(g_xhi + (pbase+r)*128 + seg);
        *(uint4*)(sXl + r*136 + seg) = *(const uint4*)(g_xlo + (pbase+r)*128 + seg);
    }
    const int nmat = dual ? 2 : 1;
    #pragma unroll 1
    for (int m = 0; m < nmat; m++) { // weight tiles, split on the fly
        const float* W = m ? WB : WA;
        __nv_bfloat16* sh = m ? sWBh : sWAh;
        __nv_bfloat16* sl = m ? sWBl : sWAl;
        #pragma unroll
        for (int q = 0; q < 16; q++) {
            int idx = tid + 256*q, row = idx >> 5, c4 = (idx & 31) << 2;
            float4 w = *(const float4*)(W + (size_t)row*128 + c4);
            __nv_bfloat16 hx=__float2bfloat16_rn(w.x), hy=__float2bfloat16_rn(w.y);
            __nv_bfloat16 hz=__float2bfloat16_rn(w.z), hw=__float2bfloat16_rn(w.w);
            __nv_bfloat162 hp0; hp0.x=hx; hp0.y=hy;
            __nv_bfloat162 hp1; hp1.x=hz; hp1.y=hw;
            __nv_bfloat162 lp0 = __floats2bfloat162_rn(w.x-__bfloat162float(hx), w.y-__bfloat162float(hy));
            __nv_bfloat162 lp1 = __floats2bfloat162_rn(w.z-__bfloat162float(hz), w.w-__bfloat162float(hw));
            *(__nv_bfloat162*)(sh + row*136 + c4)     = hp0;
            *(__nv_bfloat162*)(sh + row*136 + c4 + 2) = hp1;
            *(__nv_bfloat162*)(sl + row*136 + c4)     = lp0;
            *(__nv_bfloat162*)(sl + row*136 + c4 + 2) = lp1;
        }
    }
    __syncthreads();

    float accA[2][8][4] = {};
    gemm_tile(accA, sXh, sXl, sWAh, sWAl, lane, wm, wn);

    if (dual) {
        float accB[2][8][4] = {};
        gemm_tile(accB, sXh, sXl, sWBh, sWBl, lane, wm, wn);

        float mrow[2][2];
        #pragma unroll
        for (int mf = 0; mf < 2; mf++) {
            int r = wm*32 + mf*16 + (lane >> 2);
            mrow[mf][0] = mask[pbase + r];
            mrow[mf][1] = mask[pbase + r + 8];
        }
        __nv_bfloat16* s_stage = sWAh;  // [h=128][132] bf16, aliases WA (done)
        __syncthreads();
        #pragma unroll
        for (int mf = 0; mf < 2; mf++)
            #pragma unroll
            for (int nf = 0; nf < 8; nf++) {
                int row = wm*32 + mf*16 + (lane >> 2);
                int col = wn*64 + nf*8 + (lane & 3)*2;
                float g0 = 1.f/(1.f+__expf(-accB[mf][nf][0]));
                float g1 = 1.f/(1.f+__expf(-accB[mf][nf][1]));
                float g2 = 1.f/(1.f+__expf(-accB[mf][nf][2]));
                float g3 = 1.f/(1.f+__expf(-accB[mf][nf][3]));
                s_stage[ col   *132 + row  ] = __float2bfloat16(accA[mf][nf][0]*mrow[mf][0]*g0);
                s_stage[(col+1)*132 + row  ] = __float2bfloat16(accA[mf][nf][1]*mrow[mf][0]*g1);
                s_stage[ col   *132 + row+8] = __float2bfloat16(accA[mf][nf][2]*mrow[mf][1]*g2);
                s_stage[(col+1)*132 + row+8] = __float2bfloat16(accA[mf][nf][3]*mrow[mf][1]*g3);
            }
        __syncthreads();
        __nv_bfloat16* gdst = (mat == 0) ? g_left : g_right;
        #pragma unroll
        for (int q = 0; q < 16; q++) {
            int idx = tid + 256*q, hh = idx >> 5, seg = (idx & 31) << 2;
            *(uint2*)(gdst + (size_t)hh*PP + pbase + seg) =
                *(const uint2*)(s_stage + hh*132 + seg);
        }
    } else {
        #pragma unroll
        for (int mf = 0; mf < 2; mf++)
            #pragma unroll
            for (int nf = 0; nf < 8; nf++) {
                int row = wm*32 + mf*16 + (lane >> 2);
                int col = wn*64 + nf*8 + (lane & 3)*2;
                float2 p0 = make_float2(1.f/(1.f+__expf(-accA[mf][nf][0])),
                                        1.f/(1.f+__expf(-accA[mf][nf][1])));
                float2 p1 = make_float2(1.f/(1.f+__expf(-accA[mf][nf][2])),
                                        1.f/(1.f+__expf(-accA[mf][nf][3])));
                *(float2*)(g_ogate + (pbase+row)*128 + col)   = p0;
                *(float2*)(g_ogate + (pbase+row+8)*128 + col) = p1;
            }
    }
}

// ---------------- Stage B: per-channel bf16 einsum (unchanged) ----------------
__device__ __forceinline__ void cpa16(void* dst, const void* src) {
    unsigned u = (unsigned)__cvta_generic_to_shared(dst);
    asm volatile("cp.async.cg.shared.global [%0], [%1], 16;\n" :: "r"(u), "l"(src) : "memory");
}
__device__ __forceinline__ void sb_issue(const __nv_bfloat16* gA, const __nv_bfloat16* gB,
                                         __nv_bfloat16* sA, __nv_bfloat16* sB, int tid, int k0) {
    #pragma unroll
    for (int q = 0; q < 2; q++) {
        int idx = tid + 256*q, row = idx >> 2, seg = (idx & 3) << 3;
        cpa16(sA + row*40 + seg, gA + (size_t)row*NN + k0 + seg);
        cpa16(sB + row*40 + seg, gB + (size_t)row*NN + k0 + seg);
    }
    asm volatile("cp.async.commit_group;\n" ::: "memory");
}

__global__ __launch_bounds__(256, 2) void stage_b() {
    __shared__ __align__(16) __nv_bfloat16 smb[4*128*40];
    __nv_bfloat16* sA = smb;
    __nv_bfloat16* sB = smb + 2*128*40;

    const int tid = threadIdx.x, lane = tid & 31, warp = tid >> 5;
    const int wm = warp & 1, wn = warp >> 1;
    const int d = blockIdx.y, ti = blockIdx.x / 6, tj = blockIdx.x % 6;
    const __nv_bfloat16* gA = g_left  + (size_t)d*PP + (size_t)(ti*128)*NN;
    const __nv_bfloat16* gB = g_right + (size_t)d*PP + (size_t)(tj*128)*NN;

    float c[4][4][4] = {};
    sb_issue(gA, gB, sA, sB, tid, 0);

    #pragma unroll 1
    for (int kt = 0; kt < 24; kt++) {
        int buf = kt & 1;
        if (kt < 23) {
            sb_issue(gA, gB, sA + (buf^1)*5120, sB + (buf^1)*5120, tid, (kt+1)*32);
            asm volatile("cp.async.wait_group 1;\n" ::: "memory");
        } else {
            asm volatile("cp.async.wait_group 0;\n" ::: "memory");
        }
        __syncthreads();
        const uint32_t* At = (const uint32_t*)(sA + buf*5120);
        const uint32_t* Bt = (const uint32_t*)(sB + buf*5120);
        #pragma unroll
        for (int kk = 0; kk < 2; kk++) {
            uint32_t a[4][4], b[4][2];
            const int kw = kk*8 + (lane & 3);
            #pragma unroll
            for (int fm = 0; fm < 4; fm++) {
                int r = wm*64 + fm*16 + (lane >> 2);
                a[fm][0] = At[r*20+kw];   a[fm][1] = At[(r+8)*20+kw];
                a[fm][2] = At[r*20+kw+4]; a[fm][3] = At[(r+8)*20+kw+4];
            }
            #pragma unroll
            for (int fn = 0; fn < 4; fn++) {
                int n = wn*32 + fn*8 + (lane >> 2);
                b[fn][0] = Bt[n*20+kw]; b[fn][1] = Bt[n*20+kw+4];
            }
            #pragma unroll
            for (int fm = 0; fm < 4; fm++)
                #pragma unroll
                for (int fn = 0; fn < 4; fn++) mma16816(c[fm][fn], a[fm], b[fn]);
        }
        __syncthreads();
    }

    __nv_bfloat16* gO = g_pair + (size_t)d*PP;
    #pragma unroll
    for (int fm = 0; fm < 4; fm++)
        #pragma unroll
        for (int fn = 0; fn < 4; fn++) {
            int r0 = ti*128 + wm*64 + fm*16 + (lane >> 2);
            int cc = tj*128 + wn*32 + fn*8 + (lane & 3)*2;
            *(__nv_bfloat162*)(gO + (size_t)r0*NN + cc) =
                __float22bfloat162_rn(make_float2(c[fm][fn][0], c[fm][fn][1]));
            *(__nv_bfloat162*)(gO + (size_t)(r0+8)*NN + cc) =
                __float22bfloat162_rn(make_float2(c[fm][fn][2], c[fm][fn][3]));
        }
}

// ------------- Stage C: LN over H + out_gate + final projection (unchanged) ----
#define SC_SMEM (2*128*133*4)

__global__ __launch_bounds__(256) void stage_c(
    const float* __restrict__ onw, const float* __restrict__ onb,
    const float* __restrict__ wout, float* __restrict__ out)
{
    extern __shared__ float smc[];
    float* s_v = smc;                           // [128 pos][133]
    float* s_w = smc + 128*133;                 // [128 dout][133]
    __nv_bfloat16* s_t = (__nv_bfloat16*)s_w;   // [128 d][132] alias

    const int tid = threadIdx.x, lane = tid & 31, warp = tid >> 5;
    const int tx = tid & 15, ty = tid >> 4;
    const size_t p0 = (size_t)blockIdx.x * 128;

    #pragma unroll
    for (int q = 0; q < 16; q++) {
        int idx = tid + 256*q, dd = idx >> 5, seg = (idx & 31) << 2;
        *(uint2*)(s_t + dd*132 + seg) = *(const uint2*)(g_pair + (size_t)dd*PP + p0 + seg);
    }
    __syncthreads();

    float lw[4], lb[4];
    #pragma unroll
    for (int q = 0; q < 4; q++) { lw[q] = onw[lane+32*q]; lb[q] = onb[lane+32*q]; }

    #pragma unroll 1
    for (int pp = 0; pp < 16; pp++) {
        int pos = warp*16 + pp;
        float t[4];
        #pragma unroll
        for (int q = 0; q < 4; q++) t[q] = __bfloat162float(s_t[(lane+32*q)*132 + pos]);
        float s = t[0]+t[1]+t[2]+t[3];
        float sq = t[0]*t[0]+t[1]*t[1]+t[2]*t[2]+t[3]*t[3];
        #pragma unroll
        for (int o = 16; o; o >>= 1) {
            s  += __shfl_xor_sync(~0u, s,  o);
            sq += __shfl_xor_sync(~0u, sq, o);
        }
        float mu = s*(1.f/128.f), var = sq*(1.f/128.f) - mu*mu;
        float rstd = rsqrtf(var + 1e-5f);
        #pragma unroll
        for (int q = 0; q < 4; q++) {
            float v = (t[q]-mu)*rstd*lw[q] + lb[q];
            v *= g_ogate[(p0+pos)*128 + lane + 32*q];
            s_v[pos*133 + lane + 32*q] = v;
        }
    }
    __syncthreads();

    #pragma unroll
    for (int q = 0; q < 64; q++) {
        int idx = tid + 256*q, row = idx >> 7, cc = idx & 127;
        s_w[row*133 + cc] = wout[(size_t)row*128 + cc];
    }
    __syncthreads();

    float acc[8][8] = {};
    #pragma unroll 2
    for (int c = 0; c < 128; c++) {
        float av[8], wv[8];
        #pragma unroll
        for (int a = 0; a < 8; a++) av[a] = s_v[(ty+16*a)*133 + c];
        #pragma unroll
        for (int b = 0; b < 8; b++) wv[b] = s_w[(tx+16*b)*133 + c];
        #pragma unroll
        for (int a = 0; a < 8; a++)
            #pragma unroll
            for (int b = 0; b < 8; b++) acc[a][b] += av[a]*wv[b];
    }
    #pragma unroll
    for (int a = 0; a < 8; a++)
        #pragma unroll
        for (int b = 0; b < 8; b++)
            out[(p0 + ty + 16*a)*128 + tx + 16*b] = acc[a][b];
}

// -----------------------------------------------------------------------------
extern "C" void kernel_launch(void* const* d_in, const int* in_sizes, int n_in,
                              void* d_out, int out_size) {
    (void)in_sizes; (void)n_in; (void)out_size;
    const float* x    = (const float*)d_in[0];
    const float* mask = (const float*)d_in[1];
    const float* nw   = (const float*)d_in[2];
    const float* nb   = (const float*)d_in[3];
    const float* wl   = (const float*)d_in[4];
    const float* wr   = (const float*)d_in[5];
    const float* wlg  = (const float*)d_in[6];
    const float* wrg  = (const float*)d_in[7];
    const float* wog  = (const float*)d_in[8];
    const float* onw  = (const float*)d_in[9];
    const float* onb  = (const float*)d_in[10];
    const float* wout = (const float*)d_in[11];
    float* out = (float*)d_out;

    cudaFuncSetAttribute(stage_amm, cudaFuncAttributeMaxDynamicSharedMemorySize, AM_SMEM);
    cudaFuncSetAttribute(stage_c,   cudaFuncAttributeMaxDynamicSharedMemorySize, SC_SMEM);

    stage_ln<<<PP/64, 256>>>(x, nw, nb);
    stage_amm<<<dim3(PP/128, 3), 256, AM_SMEM>>>(mask, wl, wr, wlg, wrg, wog);
    stage_b<<<dim3(36, 128), 256>>>();
    stage_c<<<PP/128, 256, SC_SMEM>>>(onw, onb, wout, out);
}

// round 8
// speedup vs baseline: 1.7628x; 1.1949x over previous
#include <cuda_runtime.h>
#include <cuda_bf16.h>
#include <cstdint>

#define NN 768
#define PP (NN*NN)

__device__ __align__(256) __nv_bfloat16 g_xhi [(size_t)PP  * 128]; // [p][d]
__device__ __align__(256) __nv_bfloat16 g_xlo [(size_t)PP  * 128]; // [p][d]
__device__ __align__(256) __nv_bfloat16 g_left [(size_t)128 * PP]; // [h][i*N+k]
__device__ __align__(256) __nv_bfloat16 g_right[(size_t)128 * PP]; // [h][j*N+k]
__device__ __align__(256) __nv_bfloat16 g_pair [(size_t)128 * PP]; // [d][i*N+j]
__device__ __align__(256) float         g_ogate[(size_t)PP  * 128]; // [p][h]

// ---------------- Stage LN: LayerNorm + hi/lo bf16 split ----------------
__global__ __launch_bounds__(256) void stage_ln(
    const float* __restrict__ x, const float* __restrict__ nw,
    const float* __restrict__ nb)
{
    const int lane = threadIdx.x & 31, warp = threadIdx.x >> 5;
    const size_t pbase = (size_t)blockIdx.x * 64;
    float4 w4 = ((const float4*)nw)[lane], b4 = ((const float4*)nb)[lane];

    #pragma unroll 1
    for (int pp = 0; pp < 8; pp++) {
        size_t gpos = pbase + warp*8 + pp;
        float4 v = ((const float4*)(x + gpos*128))[lane];
        float s  = v.x+v.y+v.z+v.w;
        float sq = v.x*v.x+v.y*v.y+v.z*v.z+v.w*v.w;
        #pragma unroll
        for (int o = 16; o; o >>= 1) {
            s  += __shfl_xor_sync(~0u, s,  o);
            sq += __shfl_xor_sync(~0u, sq, o);
        }
        float mu = s*(1.f/128.f), var = sq*(1.f/128.f) - mu*mu;
        float rstd = rsqrtf(var + 1e-5f);
        v.x=(v.x-mu)*rstd*w4.x+b4.x; v.y=(v.y-mu)*rstd*w4.y+b4.y;
        v.z=(v.z-mu)*rstd*w4.z+b4.z; v.w=(v.w-mu)*rstd*w4.w+b4.w;
        __nv_bfloat16 hx=__float2bfloat16_rn(v.x), hy=__float2bfloat16_rn(v.y);
        __nv_bfloat16 hz=__float2bfloat16_rn(v.z), hw=__float2bfloat16_rn(v.w);
        __nv_bfloat162 h01; h01.x=hx; h01.y=hy;
        __nv_bfloat162 h23; h23.x=hz; h23.y=hw;
        __nv_bfloat162 l01 = __floats2bfloat162_rn(v.x-__bfloat162float(hx), v.y-__bfloat162float(hy));
        __nv_bfloat162 l23 = __floats2bfloat162_rn(v.z-__bfloat162float(hz), v.w-__bfloat162float(hw));
        *(__nv_bfloat162*)(g_xhi + gpos*128 + lane*4)     = h01;
        *(__nv_bfloat162*)(g_xhi + gpos*128 + lane*4 + 2) = h23;
        *(__nv_bfloat162*)(g_xlo + gpos*128 + lane*4)     = l01;
        *(__nv_bfloat162*)(g_xlo + gpos*128 + lane*4 + 2) = l23;
    }
}

// ---------------- mma helpers ----------------
__device__ __forceinline__ void mma16816(float* c, const uint32_t* a, const uint32_t* b) {
    asm volatile("mma.sync.aligned.m16n8k16.row.col.f32.bf16.bf16.f32 "
                 "{%0,%1,%2,%3}, {%4,%5,%6,%7}, {%8,%9}, {%0,%1,%2,%3};\n"
                 : "+f"(c[0]), "+f"(c[1]), "+f"(c[2]), "+f"(c[3])
                 : "r"(a[0]), "r"(a[1]), "r"(a[2]), "r"(a[3]), "r"(b[0]), "r"(b[1]));
}

// 128x128x128 split-bf16 GEMM tile: acc += X * W^T.
// 3 passes: hi*hi, hi*lo, lo*hi (lo*lo ~2^-18, dropped).
__device__ __forceinline__ void gemm_tile(
    float (&acc)[2][8][4],
    const __nv_bfloat16* sXh, const __nv_bfloat16* sXl,
    const __nv_bfloat16* sWh, const __nv_bfloat16* sWl,
    int lane, int wm, int wn)
{
    #pragma unroll 1
    for (int pass = 0; pass < 3; pass++) {
        const uint32_t* X = (const uint32_t*)((pass == 2) ? sXl : sXh);
        const uint32_t* W = (const uint32_t*)((pass == 1) ? sWl : sWh);
        #pragma unroll
        for (int ks = 0; ks < 8; ks++) {
            const int kw = ks*8 + (lane & 3);
            uint32_t a[2][4], b[8][2];
            #pragma unroll
            for (int mf = 0; mf < 2; mf++) {
                int r = wm*32 + mf*16 + (lane >> 2);
                a[mf][0]=X[r*68+kw];   a[mf][1]=X[(r+8)*68+kw];
                a[mf][2]=X[r*68+kw+4]; a[mf][3]=X[(r+8)*68+kw+4];
            }
            #pragma unroll
            for (int nf = 0; nf < 8; nf++) {
                int n = wn*64 + nf*8 + (lane >> 2);
                b[nf][0]=W[n*68+kw]; b[nf][1]=W[n*68+kw+4];
            }
            #pragma unroll
            for (int mf = 0; mf < 2; mf++)
                #pragma unroll
                for (int nf = 0; nf < 8; nf++)
                    mma16816(acc[mf][nf], a[mf], b[nf]);
        }
    }
}

// ---------------- Stage A (mma): projections + gating ----------------
#define AM_SMEM (104448*2)

__global__ __launch_bounds__(256, 1) void stage_amm(
    const float* __restrict__ mask,
    const float* __restrict__ wl, const float* __restrict__ wr,
    const float* __restrict__ wlg, const float* __restrict__ wrg,
    const float* __restrict__ wog)
{
    extern __shared__ __nv_bfloat16 smem[];
    __nv_bfloat16* sXh  = smem;            // [128][136]
    __nv_bfloat16* sXl  = smem + 17408;
    __nv_bfloat16* sWAh = smem + 34816;
    __nv_bfloat16* sWAl = smem + 52224;
    __nv_bfloat16* sWBh = smem + 69632;
    __nv_bfloat16* sWBl = smem + 87040;

    const int tid = threadIdx.x, lane = tid & 31, warp = tid >> 5;
    const int wm = warp & 3, wn = warp >> 2;
    const int mat = blockIdx.y;
    const bool dual = (mat < 2);
    const size_t pbase = (size_t)blockIdx.x * 128;
    const float* WA = (mat==0) ? wl : (mat==1) ? wr : wog;
    const float* WB = (mat==0) ? wlg : wrg;

    #pragma unroll
    for (int q = 0; q < 8; q++) { // X tiles (hi/lo)
        int idx = tid + 256*q, r = idx >> 4, seg = (idx & 15) << 3;
        *(uint4*)(sXh + r*136 + seg) = *(const uint4*)(g_xhi + (pbase+r)*128 + seg);
        *(uint4*)(sXl + r*136 + seg) = *(const uint4*)(g_xlo + (pbase+r)*128 + seg);
    }
    const int nmat = dual ? 2 : 1;
    #pragma unroll 1
    for (int m = 0; m < nmat; m++) { // weight tiles, split on the fly
        const float* W = m ? WB : WA;
        __nv_bfloat16* sh = m ? sWBh : sWAh;
        __nv_bfloat16* sl = m ? sWBl : sWAl;
        #pragma unroll
        for (int q = 0; q < 16; q++) {
            int idx = tid + 256*q, row = idx >> 5, c4 = (idx & 31) << 2;
            float4 w = *(const float4*)(W + (size_t)row*128 + c4);
            __nv_bfloat16 hx=__float2bfloat16_rn(w.x), hy=__float2bfloat16_rn(w.y);
            __nv_bfloat16 hz=__float2bfloat16_rn(w.z), hw=__float2bfloat16_rn(w.w);
            __nv_bfloat162 hp0; hp0.x=hx; hp0.y=hy;
            __nv_bfloat162 hp1; hp1.x=hz; hp1.y=hw;
            __nv_bfloat162 lp0 = __floats2bfloat162_rn(w.x-__bfloat162float(hx), w.y-__bfloat162float(hy));
            __nv_bfloat162 lp1 = __floats2bfloat162_rn(w.z-__bfloat162float(hz), w.w-__bfloat162float(hw));
            *(__nv_bfloat162*)(sh + row*136 + c4)     = hp0;
            *(__nv_bfloat162*)(sh + row*136 + c4 + 2) = hp1;
            *(__nv_bfloat162*)(sl + row*136 + c4)     = lp0;
            *(__nv_bfloat162*)(sl + row*136 + c4 + 2) = lp1;
        }
    }
    __syncthreads();

    float accA[2][8][4] = {};
    gemm_tile(accA, sXh, sXl, sWAh, sWAl, lane, wm, wn);

    if (dual) {
        float accB[2][8][4] = {};
        gemm_tile(accB, sXh, sXl, sWBh, sWBl, lane, wm, wn);

        float mrow[2][2];
        #pragma unroll
        for (int mf = 0; mf < 2; mf++) {
            int r = wm*32 + mf*16 + (lane >> 2);
            mrow[mf][0] = mask[pbase + r];
            mrow[mf][1] = mask[pbase + r + 8];
        }
        __nv_bfloat16* s_stage = sWAh;  // [h=128][132] bf16, aliases WA (done)
        __syncthreads();
        #pragma unroll
        for (int mf = 0; mf < 2; mf++)
            #pragma unroll
            for (int nf = 0; nf < 8; nf++) {
                int row = wm*32 + mf*16 + (lane >> 2);
                int col = wn*64 + nf*8 + (lane & 3)*2;
                float g0 = 1.f/(1.f+__expf(-accB[mf][nf][0]));
                float g1 = 1.f/(1.f+__expf(-accB[mf][nf][1]));
                float g2 = 1.f/(1.f+__expf(-accB[mf][nf][2]));
                float g3 = 1.f/(1.f+__expf(-accB[mf][nf][3]));
                s_stage[ col   *132 + row  ] = __float2bfloat16(accA[mf][nf][0]*mrow[mf][0]*g0);
                s_stage[(col+1)*132 + row  ] = __float2bfloat16(accA[mf][nf][1]*mrow[mf][0]*g1);
                s_stage[ col   *132 + row+8] = __float2bfloat16(accA[mf][nf][2]*mrow[mf][1]*g2);
                s_stage[(col+1)*132 + row+8] = __float2bfloat16(accA[mf][nf][3]*mrow[mf][1]*g3);
            }
        __syncthreads();
        __nv_bfloat16* gdst = (mat == 0) ? g_left : g_right;
        #pragma unroll
        for (int q = 0; q < 16; q++) {
            int idx = tid + 256*q, hh = idx >> 5, seg = (idx & 31) << 2;
            *(uint2*)(gdst + (size_t)hh*PP + pbase + seg) =
                *(const uint2*)(s_stage + hh*132 + seg);
        }
    } else {
        #pragma unroll
        for (int mf = 0; mf < 2; mf++)
            #pragma unroll
            for (int nf = 0; nf < 8; nf++) {
                int row = wm*32 + mf*16 + (lane >> 2);
                int col = wn*64 + nf*8 + (lane & 3)*2;
                float2 p0 = make_float2(1.f/(1.f+__expf(-accA[mf][nf][0])),
                                        1.f/(1.f+__expf(-accA[mf][nf][1])));
                float2 p1 = make_float2(1.f/(1.f+__expf(-accA[mf][nf][2])),
                                        1.f/(1.f+__expf(-accA[mf][nf][3])));
                *(float2*)(g_ogate + (pbase+row)*128 + col)   = p0;
                *(float2*)(g_ogate + (pbase+row+8)*128 + col) = p1;
            }
    }
}

// ---------------- Stage B: per-channel bf16 einsum (unchanged) ----------------
__device__ __forceinline__ void cpa16(void* dst, const void* src) {
    unsigned u = (unsigned)__cvta_generic_to_shared(dst);
    asm volatile("cp.async.cg.shared.global [%0], [%1], 16;\n" :: "r"(u), "l"(src) : "memory");
}
__device__ __forceinline__ void sb_issue(const __nv_bfloat16* gA, const __nv_bfloat16* gB,
                                         __nv_bfloat16* sA, __nv_bfloat16* sB, int tid, int k0) {
    #pragma unroll
    for (int q = 0; q < 2; q++) {
        int idx = tid + 256*q, row = idx >> 2, seg = (idx & 3) << 3;
        cpa16(sA + row*40 + seg, gA + (size_t)row*NN + k0 + seg);
        cpa16(sB + row*40 + seg, gB + (size_t)row*NN + k0 + seg);
    }
    asm volatile("cp.async.commit_group;\n" ::: "memory");
}

__global__ __launch_bounds__(256, 2) void stage_b() {
    __shared__ __align__(16) __nv_bfloat16 smb[4*128*40];
    __nv_bfloat16* sA = smb;
    __nv_bfloat16* sB = smb + 2*128*40;

    const int tid = threadIdx.x, lane = tid & 31, warp = tid >> 5;
    const int wm = warp & 1, wn = warp >> 1;
    const int d = blockIdx.y, ti = blockIdx.x / 6, tj = blockIdx.x % 6;
    const __nv_bfloat16* gA = g_left  + (size_t)d*PP + (size_t)(ti*128)*NN;
    const __nv_bfloat16* gB = g_right + (size_t)d*PP + (size_t)(tj*128)*NN;

    float c[4][4][4] = {};
    sb_issue(gA, gB, sA, sB, tid, 0);

    #pragma unroll 1
    for (int kt = 0; kt < 24; kt++) {
        int buf = kt & 1;
        if (kt < 23) {
            sb_issue(gA, gB, sA + (buf^1)*5120, sB + (buf^1)*5120, tid, (kt+1)*32);
            asm volatile("cp.async.wait_group 1;\n" ::: "memory");
        } else {
            asm volatile("cp.async.wait_group 0;\n" ::: "memory");
        }
        __syncthreads();
        const uint32_t* At = (const uint32_t*)(sA + buf*5120);
        const uint32_t* Bt = (const uint32_t*)(sB + buf*5120);
        #pragma unroll
        for (int kk = 0; kk < 2; kk++) {
            uint32_t a[4][4], b[4][2];
            const int kw = kk*8 + (lane & 3);
            #pragma unroll
            for (int fm = 0; fm < 4; fm++) {
                int r = wm*64 + fm*16 + (lane >> 2);
                a[fm][0] = At[r*20+kw];   a[fm][1] = At[(r+8)*20+kw];
                a[fm][2] = At[r*20+kw+4]; a[fm][3] = At[(r+8)*20+kw+4];
            }
            #pragma unroll
            for (int fn = 0; fn < 4; fn++) {
                int n = wn*32 + fn*8 + (lane >> 2);
                b[fn][0] = Bt[n*20+kw]; b[fn][1] = Bt[n*20+kw+4];
            }
            #pragma unroll
            for (int fm = 0; fm < 4; fm++)
                #pragma unroll
                for (int fn = 0; fn < 4; fn++) mma16816(c[fm][fn], a[fm], b[fn]);
        }
        __syncthreads();
    }

    __nv_bfloat16* gO = g_pair + (size_t)d*PP;
    #pragma unroll
    for (int fm = 0; fm < 4; fm++)
        #pragma unroll
        for (int fn = 0; fn < 4; fn++) {
            int r0 = ti*128 + wm*64 + fm*16 + (lane >> 2);
            int cc = tj*128 + wn*32 + fn*8 + (lane & 3)*2;
            *(__nv_bfloat162*)(gO + (size_t)r0*NN + cc) =
                __float22bfloat162_rn(make_float2(c[fm][fn][0], c[fm][fn][1]));
            *(__nv_bfloat162*)(gO + (size_t)(r0+8)*NN + cc) =
                __float22bfloat162_rn(make_float2(c[fm][fn][2], c[fm][fn][3]));
        }
}

// ------ Stage C (mma): LN over H + out_gate + final projection ------
#define SC_SMEM ((4*17408 + 16896)*2)

__global__ __launch_bounds__(256, 1) void stage_cmm(
    const float* __restrict__ onw, const float* __restrict__ onb,
    const float* __restrict__ wout, float* __restrict__ out)
{
    extern __shared__ __nv_bfloat16 smc[];
    __nv_bfloat16* s_vh = smc;           // [128 pos][136]
    __nv_bfloat16* s_vl = smc + 17408;
    __nv_bfloat16* s_wh = smc + 34816;   // [128 dout][136]
    __nv_bfloat16* s_wl = smc + 52224;
    __nv_bfloat16* s_t  = smc + 69632;   // [128 d][132] pair tile

    const int tid = threadIdx.x, lane = tid & 31, warp = tid >> 5;
    const int wm = warp & 3, wn = warp >> 2;
    const size_t p0 = (size_t)blockIdx.x * 128;

    #pragma unroll
    for (int q = 0; q < 16; q++) { // pair tile [128 d][128 pos]
        int idx = tid + 256*q, dd = idx >> 5, seg = (idx & 31) << 2;
        *(uint2*)(s_t + dd*132 + seg) = *(const uint2*)(g_pair + (size_t)dd*PP + p0 + seg);
    }
    #pragma unroll
    for (int q = 0; q < 16; q++) { // w_out split hi/lo
        int idx = tid + 256*q, row = idx >> 5, c4 = (idx & 31) << 2;
        float4 w = *(const float4*)(wout + (size_t)row*128 + c4);
        __nv_bfloat16 hx=__float2bfloat16_rn(w.x), hy=__float2bfloat16_rn(w.y);
        __nv_bfloat16 hz=__float2bfloat16_rn(w.z), hw=__float2bfloat16_rn(w.w);
        __nv_bfloat162 hp0; hp0.x=hx; hp0.y=hy;
        __nv_bfloat162 hp1; hp1.x=hz; hp1.y=hw;
        __nv_bfloat162 lp0 = __floats2bfloat162_rn(w.x-__bfloat162float(hx), w.y-__bfloat162float(hy));
        __nv_bfloat162 lp1 = __floats2bfloat162_rn(w.z-__bfloat162float(hz), w.w-__bfloat162float(hw));
        *(__nv_bfloat162*)(s_wh + row*136 + c4)     = hp0;
        *(__nv_bfloat162*)(s_wh + row*136 + c4 + 2) = hp1;
        *(__nv_bfloat162*)(s_wl + row*136 + c4)     = lp0;
        *(__nv_bfloat162*)(s_wl + row*136 + c4 + 2) = lp1;
    }
    __syncthreads();

    float lw[4], lb[4];
    #pragma unroll
    for (int q = 0; q < 4; q++) { lw[q] = onw[lane+32*q]; lb[q] = onb[lane+32*q]; }

    #pragma unroll 1
    for (int pp = 0; pp < 16; pp++) { // LN over d + gate, warp per position
        int pos = warp*16 + pp;
        float t[4];
        #pragma unroll
        for (int q = 0; q < 4; q++) t[q] = __bfloat162float(s_t[(lane+32*q)*132 + pos]);
        float s = t[0]+t[1]+t[2]+t[3];
        float sq = t[0]*t[0]+t[1]*t[1]+t[2]*t[2]+t[3]*t[3];
        #pragma unroll
        for (int o = 16; o; o >>= 1) {
            s  += __shfl_xor_sync(~0u, s,  o);
            sq += __shfl_xor_sync(~0u, sq, o);
        }
        float mu = s*(1.f/128.f), var = sq*(1.f/128.f) - mu*mu;
        float rstd = rsqrtf(var + 1e-5f);
        #pragma unroll
        for (int q = 0; q < 4; q++) {
            float v = (t[q]-mu)*rstd*lw[q] + lb[q];
            v *= g_ogate[(p0+pos)*128 + lane + 32*q];
            __nv_bfloat16 h = __float2bfloat16_rn(v);
            s_vh[pos*136 + lane + 32*q] = h;
            s_vl[pos*136 + lane + 32*q] = __float2bfloat16_rn(v - __bfloat162float(h));
        }
    }
    __syncthreads();

    float acc[2][8][4] = {};
    gemm_tile(acc, s_vh, s_vl, s_wh, s_wl, lane, wm, wn);

    #pragma unroll
    for (int mf = 0; mf < 2; mf++)
        #pragma unroll
        for (int nf = 0; nf < 8; nf++) {
            int row = wm*32 + mf*16 + (lane >> 2);
            int col = wn*64 + nf*8 + (lane & 3)*2;
            *(float2*)(out + (p0+row)*128 + col)   = make_float2(acc[mf][nf][0], acc[mf][nf][1]);
            *(float2*)(out + (p0+row+8)*128 + col) = make_float2(acc[mf][nf][2], acc[mf][nf][3]);
        }
}

// -----------------------------------------------------------------------------
extern "C" void kernel_launch(void* const* d_in, const int* in_sizes, int n_in,
                              void* d_out, int out_size) {
    (void)in_sizes; (void)n_in; (void)out_size;
    const float* x    = (const float*)d_in[0];
    const float* mask = (const float*)d_in[1];
    const float* nw   = (const float*)d_in[2];
    const float* nb   = (const float*)d_in[3];
    const float* wl   = (const float*)d_in[4];
    const float* wr   = (const float*)d_in[5];
    const float* wlg  = (const float*)d_in[6];
    const float* wrg  = (const float*)d_in[7];
    const float* wog  = (const float*)d_in[8];
    const float* onw  = (const float*)d_in[9];
    const float* onb  = (const float*)d_in[10];
    const float* wout = (const float*)d_in[11];
    float* out = (float*)d_out;

    cudaFuncSetAttribute(stage_amm, cudaFuncAttributeMaxDynamicSharedMemorySize, AM_SMEM);
    cudaFuncSetAttribute(stage_cmm, cudaFuncAttributeMaxDynamicSharedMemorySize, SC_SMEM);

    stage_ln<<<PP/64, 256>>>(x, nw, nb);
    stage_amm<<<dim3(PP/128, 3), 256, AM_SMEM>>>(mask, wl, wr, wlg, wrg, wog);
    stage_b<<<dim3(36, 128), 256>>>();
    stage_cmm<<<PP/128, 256, SC_SMEM>>>(onw, onb, wout, out);
}

// round 9
// speedup vs baseline: 1.9117x; 1.0845x over previous
#include <cuda_runtime.h>
#include <cuda_bf16.h>
#include <cstdint>

#define NN 768
#define PP (NN*NN)

__device__ __align__(256) __nv_bfloat16 g_xhi [(size_t)PP  * 128]; // [p][d]
__device__ __align__(256) __nv_bfloat16 g_xlo [(size_t)PP  * 128]; // [p][d]
__device__ __align__(256) __nv_bfloat16 g_left [(size_t)128 * PP]; // [h][i*N+k]
__device__ __align__(256) __nv_bfloat16 g_right[(size_t)128 * PP]; // [h][j*N+k]
__device__ __align__(256) __nv_bfloat16 g_pair [(size_t)128 * PP]; // [d][i*N+j]
__device__ __align__(256) float         g_ogate[(size_t)PP  * 128]; // [p][h]

// ---------------- Stage LN: LayerNorm + hi/lo bf16 split ----------------
__global__ __launch_bounds__(256) void stage_ln(
    const float* __restrict__ x, const float* __restrict__ nw,
    const float* __restrict__ nb)
{
    const int lane = threadIdx.x & 31, warp = threadIdx.x >> 5;
    const size_t pbase = (size_t)blockIdx.x * 64;
    float4 w4 = ((const float4*)nw)[lane], b4 = ((const float4*)nb)[lane];

    #pragma unroll 1
    for (int pp = 0; pp < 8; pp++) {
        size_t gpos = pbase + warp*8 + pp;
        float4 v = ((const float4*)(x + gpos*128))[lane];
        float s  = v.x+v.y+v.z+v.w;
        float sq = v.x*v.x+v.y*v.y+v.z*v.z+v.w*v.w;
        #pragma unroll
        for (int o = 16; o; o >>= 1) {
            s  += __shfl_xor_sync(~0u, s,  o);
            sq += __shfl_xor_sync(~0u, sq, o);
        }
        float mu = s*(1.f/128.f), var = sq*(1.f/128.f) - mu*mu;
        float rstd = rsqrtf(var + 1e-5f);
        v.x=(v.x-mu)*rstd*w4.x+b4.x; v.y=(v.y-mu)*rstd*w4.y+b4.y;
        v.z=(v.z-mu)*rstd*w4.z+b4.z; v.w=(v.w-mu)*rstd*w4.w+b4.w;
        __nv_bfloat16 hx=__float2bfloat16_rn(v.x), hy=__float2bfloat16_rn(v.y);
        __nv_bfloat16 hz=__float2bfloat16_rn(v.z), hw=__float2bfloat16_rn(v.w);
        __nv_bfloat162 h01; h01.x=hx; h01.y=hy;
        __nv_bfloat162 h23; h23.x=hz; h23.y=hw;
        __nv_bfloat162 l01 = __floats2bfloat162_rn(v.x-__bfloat162float(hx), v.y-__bfloat162float(hy));
        __nv_bfloat162 l23 = __floats2bfloat162_rn(v.z-__bfloat162float(hz), v.w-__bfloat162float(hw));
        *(__nv_bfloat162*)(g_xhi + gpos*128 + lane*4)     = h01;
        *(__nv_bfloat162*)(g_xhi + gpos*128 + lane*4 + 2) = h23;
        *(__nv_bfloat162*)(g_xlo + gpos*128 + lane*4)     = l01;
        *(__nv_bfloat162*)(g_xlo + gpos*128 + lane*4 + 2) = l23;
    }
}

// ---------------- mma helpers ----------------
__device__ __forceinline__ void mma16816(float* c, const uint32_t* a, const uint32_t* b) {
    asm volatile("mma.sync.aligned.m16n8k16.row.col.f32.bf16.bf16.f32 "
                 "{%0,%1,%2,%3}, {%4,%5,%6,%7}, {%8,%9}, {%0,%1,%2,%3};\n"
                 : "+f"(c[0]), "+f"(c[1]), "+f"(c[2]), "+f"(c[3])
                 : "r"(a[0]), "r"(a[1]), "r"(a[2]), "r"(a[3]), "r"(b[0]), "r"(b[1]));
}
__device__ __forceinline__ void ldsm4(uint32_t* r, const void* p) {
    unsigned a = (unsigned)__cvta_generic_to_shared(p);
    asm volatile("ldmatrix.sync.aligned.m8n8.x4.shared.b16 {%0,%1,%2,%3}, [%4];\n"
                 : "=r"(r[0]), "=r"(r[1]), "=r"(r[2]), "=r"(r[3]) : "r"(a));
}

// M(2x16) x N(NF x 8) x K128 split-bf16 GEMM tile: acc += X * W^T.
// 3 passes: hi*hi, hi*lo, lo*hi (lo*lo ~2^-18, dropped). Pitch = 136 bf16.
template<int NF>
__device__ __forceinline__ void gemm_tile_t(
    float (&acc)[2][NF][4],
    const __nv_bfloat16* sXh, const __nv_bfloat16* sXl,
    const __nv_bfloat16* sWh, const __nv_bfloat16* sWl,
    int lane, int mbase, int nbase)
{
    const int lr  = lane & 15, lkA = (lane >> 4) << 3;       // A ldsm addressing
    const int bn  = lane & 7, bks = ((lane >> 3) & 1) << 3;  // B ldsm addressing
    const int bnf = lane >> 4;
    #pragma unroll 1
    for (int pass = 0; pass < 3; pass++) {
        const __nv_bfloat16* X = (pass == 2) ? sXl : sXh;
        const __nv_bfloat16* W = (pass == 1) ? sWl : sWh;
        #pragma unroll
        for (int ks = 0; ks < 8; ks++) {
            uint32_t a[2][4], b[NF][2];
            #pragma unroll
            for (int mf = 0; mf < 2; mf++)
                ldsm4(a[mf], X + (mbase + mf*16 + lr)*136 + ks*16 + lkA);
            #pragma unroll
            for (int nf = 0; nf < NF; nf += 2) {
                uint32_t t[4];
                ldsm4(t, W + (nbase + (nf + bnf)*8 + bn)*136 + ks*16 + bks);
                b[nf][0]=t[0]; b[nf][1]=t[1]; b[nf+1][0]=t[2]; b[nf+1][1]=t[3];
            }
            #pragma unroll
            for (int mf = 0; mf < 2; mf++)
                #pragma unroll
                for (int nf = 0; nf < NF; nf++)
                    mma16816(acc[mf][nf], a[mf], b[nf]);
        }
    }
}

// ---------------- Stage A (mma): projections + gating ----------------
#define AM_SMEM (104448*2)

__global__ __launch_bounds__(256, 1) void stage_amm(
    const float* __restrict__ mask,
    const float* __restrict__ wl, const float* __restrict__ wr,
    const float* __restrict__ wlg, const float* __restrict__ wrg,
    const float* __restrict__ wog)
{
    extern __shared__ __nv_bfloat16 smem[];
    __nv_bfloat16* sXh  = smem;            // [128][136]
    __nv_bfloat16* sXl  = smem + 17408;
    __nv_bfloat16* sWAh = smem + 34816;
    __nv_bfloat16* sWAl = smem + 52224;
    __nv_bfloat16* sWBh = smem + 69632;
    __nv_bfloat16* sWBl = smem + 87040;

    const int tid = threadIdx.x, lane = tid & 31, warp = tid >> 5;
    const int wm = warp & 3, wn = warp >> 2;
    const int mat = blockIdx.y;
    const bool dual = (mat < 2);
    const size_t pbase = (size_t)blockIdx.x * 128;
    const float* WA = (mat==0) ? wl : (mat==1) ? wr : wog;
    const float* WB = (mat==0) ? wlg : wrg;

    #pragma unroll
    for (int q = 0; q < 8; q++) { // X tiles (hi/lo)
        int idx = tid + 256*q, r = idx >> 4, seg = (idx & 15) << 3;
        *(uint4*)(sXh + r*136 + seg) = *(const uint4*)(g_xhi + (pbase+r)*128 + seg);
        *(uint4*)(sXl + r*136 + seg) = *(const uint4*)(g_xlo + (pbase+r)*128 + seg);
    }
    const int nmat = dual ? 2 : 1;
    #pragma unroll 1
    for (int m = 0; m < nmat; m++) { // weight tiles, split on the fly
        const float* W = m ? WB : WA;
        __nv_bfloat16* sh = m ? sWBh : sWAh;
        __nv_bfloat16* sl = m ? sWBl : sWAl;
        #pragma unroll
        for (int q = 0; q < 16; q++) {
            int idx = tid + 256*q, row = idx >> 5, c4 = (idx & 31) << 2;
            float4 w = *(const float4*)(W + (size_t)row*128 + c4);
            __nv_bfloat16 hx=__float2bfloat16_rn(w.x), hy=__float2bfloat16_rn(w.y);
            __nv_bfloat16 hz=__float2bfloat16_rn(w.z), hw=__float2bfloat16_rn(w.w);
            __nv_bfloat162 hp0; hp0.x=hx; hp0.y=hy;
            __nv_bfloat162 hp1; hp1.x=hz; hp1.y=hw;
            __nv_bfloat162 lp0 = __floats2bfloat162_rn(w.x-__bfloat162float(hx), w.y-__bfloat162float(hy));
            __nv_bfloat162 lp1 = __floats2bfloat162_rn(w.z-__bfloat162float(hz), w.w-__bfloat162float(hw));
            *(__nv_bfloat162*)(sh + row*136 + c4)     = hp0;
            *(__nv_bfloat162*)(sh + row*136 + c4 + 2) = hp1;
            *(__nv_bfloat162*)(sl + row*136 + c4)     = lp0;
            *(__nv_bfloat162*)(sl + row*136 + c4 + 2) = lp1;
        }
    }
    __syncthreads();

    float accA[2][8][4] = {};
    gemm_tile_t<8>(accA, sXh, sXl, sWAh, sWAl, lane, wm*32, wn*64);

    if (dual) {
        float accB[2][8][4] = {};
        gemm_tile_t<8>(accB, sXh, sXl, sWBh, sWBl, lane, wm*32, wn*64);

        float mrow[2][2];
        #pragma unroll
        for (int mf = 0; mf < 2; mf++) {
            int r = wm*32 + mf*16 + (lane >> 2);
            mrow[mf][0] = mask[pbase + r];
            mrow[mf][1] = mask[pbase + r + 8];
        }
        __nv_bfloat16* s_stage = sWAh;  // [h=128][132] bf16, aliases WA (done)
        __syncthreads();
        #pragma unroll
        for (int mf = 0; mf < 2; mf++)
            #pragma unroll
            for (int nf = 0; nf < 8; nf++) {
                int row = wm*32 + mf*16 + (lane >> 2);
                int col = wn*64 + nf*8 + (lane & 3)*2;
                float g0 = 1.f/(1.f+__expf(-accB[mf][nf][0]));
                float g1 = 1.f/(1.f+__expf(-accB[mf][nf][1]));
                float g2 = 1.f/(1.f+__expf(-accB[mf][nf][2]));
                float g3 = 1.f/(1.f+__expf(-accB[mf][nf][3]));
                s_stage[ col   *132 + row  ] = __float2bfloat16(accA[mf][nf][0]*mrow[mf][0]*g0);
                s_stage[(col+1)*132 + row  ] = __float2bfloat16(accA[mf][nf][1]*mrow[mf][0]*g1);
                s_stage[ col   *132 + row+8] = __float2bfloat16(accA[mf][nf][2]*mrow[mf][1]*g2);
                s_stage[(col+1)*132 + row+8] = __float2bfloat16(accA[mf][nf][3]*mrow[mf][1]*g3);
            }
        __syncthreads();
        __nv_bfloat16* gdst = (mat == 0) ? g_left : g_right;
        #pragma unroll
        for (int q = 0; q < 16; q++) {
            int idx = tid + 256*q, hh = idx >> 5, seg = (idx & 31) << 2;
            *(uint2*)(gdst + (size_t)hh*PP + pbase + seg) =
                *(const uint2*)(s_stage + hh*132 + seg);
        }
    } else {
        #pragma unroll
        for (int mf = 0; mf < 2; mf++)
            #pragma unroll
            for (int nf = 0; nf < 8; nf++) {
                int row = wm*32 + mf*16 + (lane >> 2);
                int col = wn*64 + nf*8 + (lane & 3)*2;
                float2 p0 = make_float2(1.f/(1.f+__expf(-accA[mf][nf][0])),
                                        1.f/(1.f+__expf(-accA[mf][nf][1])));
                float2 p1 = make_float2(1.f/(1.f+__expf(-accA[mf][nf][2])),
                                        1.f/(1.f+__expf(-accA[mf][nf][3])));
                *(float2*)(g_ogate + (pbase+row)*128 + col)   = p0;
                *(float2*)(g_ogate + (pbase+row+8)*128 + col) = p1;
            }
    }
}

// ---------------- Stage B: per-channel bf16 einsum (unchanged) ----------------
__device__ __forceinline__ void cpa16(void* dst, const void* src) {
    unsigned u = (unsigned)__cvta_generic_to_shared(dst);
    asm volatile("cp.async.cg.shared.global [%0], [%1], 16;\n" :: "r"(u), "l"(src) : "memory");
}
__device__ __forceinline__ void sb_issue(const __nv_bfloat16* gA, const __nv_bfloat16* gB,
                                         __nv_bfloat16* sA, __nv_bfloat16* sB, int tid, int k0) {
    #pragma unroll
    for (int q = 0; q < 2; q++) {
        int idx = tid + 256*q, row = idx >> 2, seg = (idx & 3) << 3;
        cpa16(sA + row*40 + seg, gA + (size_t)row*NN + k0 + seg);
        cpa16(sB + row*40 + seg, gB + (size_t)row*NN + k0 + seg);
    }
    asm volatile("cp.async.commit_group;\n" ::: "memory");
}

__global__ __launch_bounds__(256, 2) void stage_b() {
    __shared__ __align__(16) __nv_bfloat16 smb[4*128*40];
    __nv_bfloat16* sA = smb;
    __nv_bfloat16* sB = smb + 2*128*40;

    const int tid = threadIdx.x, lane = tid & 31, warp = tid >> 5;
    const int wm = warp & 1, wn = warp >> 1;
    const int d = blockIdx.y, ti = blockIdx.x / 6, tj = blockIdx.x % 6;
    const __nv_bfloat16* gA = g_left  + (size_t)d*PP + (size_t)(ti*128)*NN;
    const __nv_bfloat16* gB = g_right + (size_t)d*PP + (size_t)(tj*128)*NN;

    float c[4][4][4] = {};
    sb_issue(gA, gB, sA, sB, tid, 0);

    #pragma unroll 1
    for (int kt = 0; kt < 24; kt++) {
        int buf = kt & 1;
        if (kt < 23) {
            sb_issue(gA, gB, sA + (buf^1)*5120, sB + (buf^1)*5120, tid, (kt+1)*32);
            asm volatile("cp.async.wait_group 1;\n" ::: "memory");
        } else {
            asm volatile("cp.async.wait_group 0;\n" ::: "memory");
        }
        __syncthreads();
        const uint32_t* At = (const uint32_t*)(sA + buf*5120);
        const uint32_t* Bt = (const uint32_t*)(sB + buf*5120);
        #pragma unroll
        for (int kk = 0; kk < 2; kk++) {
            uint32_t a[4][4], b[4][2];
            const int kw = kk*8 + (lane & 3);
            #pragma unroll
            for (int fm = 0; fm < 4; fm++) {
                int r = wm*64 + fm*16 + (lane >> 2);
                a[fm][0] = At[r*20+kw];   a[fm][1] = At[(r+8)*20+kw];
                a[fm][2] = At[r*20+kw+4]; a[fm][3] = At[(r+8)*20+kw+4];
            }
            #pragma unroll
            for (int fn = 0; fn < 4; fn++) {
                int n = wn*32 + fn*8 + (lane >> 2);
                b[fn][0] = Bt[n*20+kw]; b[fn][1] = Bt[n*20+kw+4];
            }
            #pragma unroll
            for (int fm = 0; fm < 4; fm++)
                #pragma unroll
                for (int fn = 0; fn < 4; fn++) mma16816(c[fm][fn], a[fm], b[fn]);
        }
        __syncthreads();
    }

    __nv_bfloat16* gO = g_pair + (size_t)d*PP;
    #pragma unroll
    for (int fm = 0; fm < 4; fm++)
        #pragma unroll
        for (int fn = 0; fn < 4; fn++) {
            int r0 = ti*128 + wm*64 + fm*16 + (lane >> 2);
            int cc = tj*128 + wn*32 + fn*8 + (lane & 3)*2;
            *(__nv_bfloat162*)(gO + (size_t)r0*NN + cc) =
                __float22bfloat162_rn(make_float2(c[fm][fn][0], c[fm][fn][1]));
            *(__nv_bfloat162*)(gO + (size_t)(r0+8)*NN + cc) =
                __float22bfloat162_rn(make_float2(c[fm][fn][2], c[fm][fn][3]));
        }
}

// ------ Stage C (mma): LN over H + out_gate + final projection, M=64 ------
#define SC_SMEM (2*17408 + 2*34816)   // 102 KB -> 2 CTAs/SM

__global__ __launch_bounds__(256, 2) void stage_cmm(
    const float* __restrict__ onw, const float* __restrict__ onb,
    const float* __restrict__ wout, float* __restrict__ out)
{
    extern __shared__ __nv_bfloat16 smc[];
    __nv_bfloat16* s_vh = smc;            // [64 pos][136]
    __nv_bfloat16* s_vl = smc + 8704;
    __nv_bfloat16* s_wh = smc + 17408;    // [128 dout][136]
    __nv_bfloat16* s_wl = smc + 34816;
    __nv_bfloat16* s_t  = s_wh;           // [128 d][68] overlay, dead before w fill

    const int tid = threadIdx.x, lane = tid & 31, warp = tid >> 5;
    const int wm = warp & 1, wn = warp >> 1;
    const size_t p0 = (size_t)blockIdx.x * 64;

    #pragma unroll
    for (int q = 0; q < 8; q++) { // pair tile [128 d][64 pos]
        int idx = tid + 256*q, dd = idx >> 4, seg = (idx & 15) << 2;
        *(uint2*)(s_t + dd*68 + seg) = *(const uint2*)(g_pair + (size_t)dd*PP + p0 + seg);
    }
    __syncthreads();

    float lw[4], lb[4];
    #pragma unroll
    for (int q = 0; q < 4; q++) { lw[q] = onw[lane+32*q]; lb[q] = onb[lane+32*q]; }

    #pragma unroll 1
    for (int pp = 0; pp < 8; pp++) { // LN over d + gate, warp per position
        int pos = warp*8 + pp;
        float t[4];
        #pragma unroll
        for (int q = 0; q < 4; q++) t[q] = __bfloat162float(s_t[(lane+32*q)*68 + pos]);
        float s = t[0]+t[1]+t[2]+t[3];
        float sq = t[0]*t[0]+t[1]*t[1]+t[2]*t[2]+t[3]*t[3];
        #pragma unroll
        for (int o = 16; o; o >>= 1) {
            s  += __shfl_xor_sync(~0u, s,  o);
            sq += __shfl_xor_sync(~0u, sq, o);
        }
        float mu = s*(1.f/128.f), var = sq*(1.f/128.f) - mu*mu;
        float rstd = rsqrtf(var + 1e-5f);
        #pragma unroll
        for (int q = 0; q < 4; q++) {
            float v = (t[q]-mu)*rstd*lw[q] + lb[q];
            v *= g_ogate[(p0+pos)*128 + lane + 32*q];
            __nv_bfloat16 h = __float2bfloat16_rn(v);
            s_vh[pos*136 + lane + 32*q] = h;
            s_vl[pos*136 + lane + 32*q] = __float2bfloat16_rn(v - __bfloat162float(h));
        }
    }
    __syncthreads();  // LN reads of s_t done; safe to overwrite with w_out

    #pragma unroll
    for (int q = 0; q < 16; q++) { // w_out split hi/lo
        int idx = tid + 256*q, row = idx >> 5, c4 = (idx & 31) << 2;
        float4 w = *(const float4*)(wout + (size_t)row*128 + c4);
        __nv_bfloat16 hx=__float2bfloat16_rn(w.x), hy=__float2bfloat16_rn(w.y);
        __nv_bfloat16 hz=__float2bfloat16_rn(w.z), hw=__float2bfloat16_rn(w.w);
        __nv_bfloat162 hp0; hp0.x=hx; hp0.y=hy;
        __nv_bfloat162 hp1; hp1.x=hz; hp1.y=hw;
        __nv_bfloat162 lp0 = __floats2bfloat162_rn(w.x-__bfloat162float(hx), w.y-__bfloat162float(hy));
        __nv_bfloat162 lp1 = __floats2bfloat162_rn(w.z-__bfloat162float(hz), w.w-__bfloat162float(hw));
        *(__nv_bfloat162*)(s_wh + row*136 + c4)     = hp0;
        *(__nv_bfloat162*)(s_wh + row*136 + c4 + 2) = hp1;
        *(__nv_bfloat162*)(s_wl + row*136 + c4)     = lp0;
        *(__nv_bfloat162*)(s_wl + row*136 + c4 + 2) = lp1;
    }
    __syncthreads();

    float acc[2][4][4] = {};
    gemm_tile_t<4>(acc, s_vh, s_vl, s_wh, s_wl, lane, wm*32, wn*32);

    #pragma unroll
    for (int mf = 0; mf < 2; mf++)
        #pragma unroll
        for (int nf = 0; nf < 4; nf++) {
            int row = wm*32 + mf*16 + (lane >> 2);
            int col = wn*32 + nf*8 + (lane & 3)*2;
            *(float2*)(out + (p0+row)*128 + col)   = make_float2(acc[mf][nf][0], acc[mf][nf][1]);
            *(float2*)(out + (p0+row+8)*128 + col) = make_float2(acc[mf][nf][2], acc[mf][nf][3]);
        }
}

// -----------------------------------------------------------------------------
extern "C" void kernel_launch(void* const* d_in, const int* in_sizes, int n_in,
                              void* d_out, int out_size) {
    (void)in_sizes; (void)n_in; (void)out_size;
    const float* x    = (const float*)d_in[0];
    const float* mask = (const float*)d_in[1];
    const float* nw   = (const float*)d_in[2];
    const float* nb   = (const float*)d_in[3];
    const float* wl   = (const float*)d_in[4];
    const float* wr   = (const float*)d_in[5];
    const float* wlg  = (const float*)d_in[6];
    const float* wrg  = (const float*)d_in[7];
    const float* wog  = (const float*)d_in[8];
    const float* onw  = (const float*)d_in[9];
    const float* onb  = (const float*)d_in[10];
    const float* wout = (const float*)d_in[11];
    float* out = (float*)d_out;

    cudaFuncSetAttribute(stage_amm, cudaFuncAttributeMaxDynamicSharedMemorySize, AM_SMEM);
    cudaFuncSetAttribute(stage_cmm, cudaFuncAttributeMaxDynamicSharedMemorySize, SC_SMEM);

    stage_ln<<<PP/64, 256>>>(x, nw, nb);
    stage_amm<<<dim3(PP/128, 3), 256, AM_SMEM>>>(mask, wl, wr, wlg, wrg, wog);
    stage_b<<<dim3(36, 128), 256>>>();
    stage_cmm<<<PP/64, 256, SC_SMEM>>>(onw, onb, wout, out);
}

// round 10
// speedup vs baseline: 2.1365x; 1.1176x over previous
#include <cuda_runtime.h>
#include <cuda_bf16.h>
#include <cstdint>

#define NN 768
#define PP (NN*NN)

__device__ __align__(256) __nv_bfloat16 g_xhi [(size_t)PP  * 128]; // [p][d]
__device__ __align__(256) __nv_bfloat16 g_xlo [(size_t)PP  * 128]; // [p][d]
__device__ __align__(256) __nv_bfloat16 g_left [(size_t)128 * PP]; // [h][i*N+k]
__device__ __align__(256) __nv_bfloat16 g_right[(size_t)128 * PP]; // [h][j*N+k]
__device__ __align__(256) __nv_bfloat16 g_pair [(size_t)128 * PP]; // [d][i*N+j]
__device__ __align__(256) float         g_ogate[(size_t)PP  * 128]; // [p][h]

// ---------------- Stage LN: LayerNorm + hi/lo bf16 split ----------------
__global__ __launch_bounds__(256) void stage_ln(
    const float* __restrict__ x, const float* __restrict__ nw,
    const float* __restrict__ nb)
{
    const int lane = threadIdx.x & 31, warp = threadIdx.x >> 5;
    const size_t pbase = (size_t)blockIdx.x * 64;
    float4 w4 = ((const float4*)nw)[lane], b4 = ((const float4*)nb)[lane];

    #pragma unroll 1
    for (int pp = 0; pp < 8; pp++) {
        size_t gpos = pbase + warp*8 + pp;
        float4 v = ((const float4*)(x + gpos*128))[lane];
        float s  = v.x+v.y+v.z+v.w;
        float sq = v.x*v.x+v.y*v.y+v.z*v.z+v.w*v.w;
        #pragma unroll
        for (int o = 16; o; o >>= 1) {
            s  += __shfl_xor_sync(~0u, s,  o);
            sq += __shfl_xor_sync(~0u, sq, o);
        }
        float mu = s*(1.f/128.f), var = sq*(1.f/128.f) - mu*mu;
        float rstd = rsqrtf(var + 1e-5f);
        v.x=(v.x-mu)*rstd*w4.x+b4.x; v.y=(v.y-mu)*rstd*w4.y+b4.y;
        v.z=(v.z-mu)*rstd*w4.z+b4.z; v.w=(v.w-mu)*rstd*w4.w+b4.w;
        __nv_bfloat16 hx=__float2bfloat16_rn(v.x), hy=__float2bfloat16_rn(v.y);
        __nv_bfloat16 hz=__float2bfloat16_rn(v.z), hw=__float2bfloat16_rn(v.w);
        __nv_bfloat162 h01; h01.x=hx; h01.y=hy;
        __nv_bfloat162 h23; h23.x=hz; h23.y=hw;
        __nv_bfloat162 l01 = __floats2bfloat162_rn(v.x-__bfloat162float(hx), v.y-__bfloat162float(hy));
        __nv_bfloat162 l23 = __floats2bfloat162_rn(v.z-__bfloat162float(hz), v.w-__bfloat162float(hw));
        *(__nv_bfloat162*)(g_xhi + gpos*128 + lane*4)     = h01;
        *(__nv_bfloat162*)(g_xhi + gpos*128 + lane*4 + 2) = h23;
        *(__nv_bfloat162*)(g_xlo + gpos*128 + lane*4)     = l01;
        *(__nv_bfloat162*)(g_xlo + gpos*128 + lane*4 + 2) = l23;
    }
}

// ---------------- mma helpers ----------------
__device__ __forceinline__ void mma16816(float* c, const uint32_t* a, const uint32_t* b) {
    asm volatile("mma.sync.aligned.m16n8k16.row.col.f32.bf16.bf16.f32 "
                 "{%0,%1,%2,%3}, {%4,%5,%6,%7}, {%8,%9}, {%0,%1,%2,%3};\n"
                 : "+f"(c[0]), "+f"(c[1]), "+f"(c[2]), "+f"(c[3])
                 : "r"(a[0]), "r"(a[1]), "r"(a[2]), "r"(a[3]), "r"(b[0]), "r"(b[1]));
}
__device__ __forceinline__ void ldsm4(uint32_t* r, const void* p) {
    unsigned a = (unsigned)__cvta_generic_to_shared(p);
    asm volatile("ldmatrix.sync.aligned.m8n8.x4.shared.b16 {%0,%1,%2,%3}, [%4];\n"
                 : "=r"(r[0]), "=r"(r[1]), "=r"(r[2]), "=r"(r[3]) : "r"(a));
}

// M(2x16) x N(NF x 8) x K128 split-bf16 GEMM tile: acc += X * W^T.
// 3 passes: hi*hi, hi*lo, lo*hi (lo*lo ~2^-18, dropped). Pitch = 136 bf16.
template<int NF>
__device__ __forceinline__ void gemm_tile_t(
    float (&acc)[2][NF][4],
    const __nv_bfloat16* sXh, const __nv_bfloat16* sXl,
    const __nv_bfloat16* sWh, const __nv_bfloat16* sWl,
    int lane, int mbase, int nbase)
{
    const int lr  = lane & 15, lkA = (lane >> 4) << 3;       // A ldsm addressing
    const int bn  = lane & 7, bks = ((lane >> 3) & 1) << 3;  // B ldsm addressing
    const int bnf = lane >> 4;
    #pragma unroll 1
    for (int pass = 0; pass < 3; pass++) {
        const __nv_bfloat16* X = (pass == 2) ? sXl : sXh;
        const __nv_bfloat16* W = (pass == 1) ? sWl : sWh;
        #pragma unroll
        for (int ks = 0; ks < 8; ks++) {
            uint32_t a[2][4], b[NF][2];
            #pragma unroll
            for (int mf = 0; mf < 2; mf++)
                ldsm4(a[mf], X + (mbase + mf*16 + lr)*136 + ks*16 + lkA);
            #pragma unroll
            for (int nf = 0; nf < NF; nf += 2) {
                uint32_t t[4];
                ldsm4(t, W + (nbase + (nf + bnf)*8 + bn)*136 + ks*16 + bks);
                b[nf][0]=t[0]; b[nf][1]=t[1]; b[nf+1][0]=t[2]; b[nf+1][1]=t[3];
            }
            #pragma unroll
            for (int mf = 0; mf < 2; mf++)
                #pragma unroll
                for (int nf = 0; nf < NF; nf++)
                    mma16816(acc[mf][nf], a[mf], b[nf]);
        }
    }
}

// split a [128][128] fp32 weight matrix into bf16 hi/lo smem tiles, pitch 136
__device__ __forceinline__ void split_w128(const float* __restrict__ W,
                                           __nv_bfloat16* sh, __nv_bfloat16* sl, int tid) {
    #pragma unroll
    for (int q = 0; q < 16; q++) {
        int idx = tid + 256*q, row = idx >> 5, c4 = (idx & 31) << 2;
        float4 w = *(const float4*)(W + (size_t)row*128 + c4);
        __nv_bfloat16 hx=__float2bfloat16_rn(w.x), hy=__float2bfloat16_rn(w.y);
        __nv_bfloat16 hz=__float2bfloat16_rn(w.z), hw=__float2bfloat16_rn(w.w);
        __nv_bfloat162 hp0; hp0.x=hx; hp0.y=hy;
        __nv_bfloat162 hp1; hp1.x=hz; hp1.y=hw;
        __nv_bfloat162 lp0 = __floats2bfloat162_rn(w.x-__bfloat162float(hx), w.y-__bfloat162float(hy));
        __nv_bfloat162 lp1 = __floats2bfloat162_rn(w.z-__bfloat162float(hz), w.w-__bfloat162float(hw));
        *(__nv_bfloat162*)(sh + row*136 + c4)     = hp0;
        *(__nv_bfloat162*)(sh + row*136 + c4 + 2) = hp1;
        *(__nv_bfloat162*)(sl + row*136 + c4)     = lp0;
        *(__nv_bfloat162*)(sl + row*136 + c4 + 2) = lp1;
    }
}

// ------- Stage A (mma): projections + gating, M=64, 2 CTAs/SM -------
#define AM_SMEM (2*17408 + 2*34816)   // 102 KB

__global__ __launch_bounds__(256, 2) void stage_amm(
    const float* __restrict__ mask,
    const float* __restrict__ wl, const float* __restrict__ wr,
    const float* __restrict__ wlg, const float* __restrict__ wrg,
    const float* __restrict__ wog)
{
    extern __shared__ __nv_bfloat16 smem[];
    __nv_bfloat16* sXh = smem;            // [64][136]
    __nv_bfloat16* sXl = smem + 8704;
    __nv_bfloat16* sWh = smem + 17408;    // [128][136]
    __nv_bfloat16* sWl = smem + 34816;

    const int tid = threadIdx.x, lane = tid & 31, warp = tid >> 5;
    const int wm = warp & 1, wn = warp >> 1;
    const int mat = blockIdx.y;
    const bool dual = (mat < 2);
    const size_t pbase = (size_t)blockIdx.x * 64;
    const float* WA = (mat==0) ? wl : (mat==1) ? wr : wog;
    const float* WB = (mat==0) ? wlg : wrg;

    #pragma unroll
    for (int q = 0; q < 4; q++) { // X tiles (hi/lo), 64 rows
        int idx = tid + 256*q, r = idx >> 4, seg = (idx & 15) << 3;
        *(uint4*)(sXh + r*136 + seg) = *(const uint4*)(g_xhi + (pbase+r)*128 + seg);
        *(uint4*)(sXl + r*136 + seg) = *(const uint4*)(g_xlo + (pbase+r)*128 + seg);
    }
    split_w128(WA, sWh, sWl, tid);
    __syncthreads();

    float accA[2][4][4] = {};
    gemm_tile_t<4>(accA, sXh, sXl, sWh, sWl, lane, wm*32, wn*32);

    if (dual) {
        __syncthreads();                 // all WA reads done
        split_w128(WB, sWh, sWl, tid);
        __syncthreads();
        float accB[2][4][4] = {};
        gemm_tile_t<4>(accB, sXh, sXl, sWh, sWl, lane, wm*32, wn*32);

        float mrow[2][2];
        #pragma unroll
        for (int mf = 0; mf < 2; mf++) {
            int r = wm*32 + mf*16 + (lane >> 2);
            mrow[mf][0] = mask[pbase + r];
            mrow[mf][1] = mask[pbase + r + 8];
        }
        __nv_bfloat16* s_stage = sXh;    // [128 h][68 pos], X dead after gemms
        __syncthreads();
        #pragma unroll
        for (int mf = 0; mf < 2; mf++)
            #pragma unroll
            for (int nf = 0; nf < 4; nf++) {
                int row = wm*32 + mf*16 + (lane >> 2);
                int col = wn*32 + nf*8 + (lane & 3)*2;
                float g0 = 1.f/(1.f+__expf(-accB[mf][nf][0]));
                float g1 = 1.f/(1.f+__expf(-accB[mf][nf][1]));
                float g2 = 1.f/(1.f+__expf(-accB[mf][nf][2]));
                float g3 = 1.f/(1.f+__expf(-accB[mf][nf][3]));
                s_stage[ col   *68 + row  ] = __float2bfloat16(accA[mf][nf][0]*mrow[mf][0]*g0);
                s_stage[(col+1)*68 + row  ] = __float2bfloat16(accA[mf][nf][1]*mrow[mf][0]*g1);
                s_stage[ col   *68 + row+8] = __float2bfloat16(accA[mf][nf][2]*mrow[mf][1]*g2);
                s_stage[(col+1)*68 + row+8] = __float2bfloat16(accA[mf][nf][3]*mrow[mf][1]*g3);
            }
        __syncthreads();
        __nv_bfloat16* gdst = (mat == 0) ? g_left : g_right;
        #pragma unroll
        for (int q = 0; q < 8; q++) {
            int idx = tid + 256*q, hh = idx >> 4, seg = (idx & 15) << 2;
            *(uint2*)(gdst + (size_t)hh*PP + pbase + seg) =
                *(const uint2*)(s_stage + hh*68 + seg);
        }
    } else {
        #pragma unroll
        for (int mf = 0; mf < 2; mf++)
            #pragma unroll
            for (int nf = 0; nf < 4; nf++) {
                int row = wm*32 + mf*16 + (lane >> 2);
                int col = wn*32 + nf*8 + (lane & 3)*2;
                float2 p0 = make_float2(1.f/(1.f+__expf(-accA[mf][nf][0])),
                                        1.f/(1.f+__expf(-accA[mf][nf][1])));
                float2 p1 = make_float2(1.f/(1.f+__expf(-accA[mf][nf][2])),
                                        1.f/(1.f+__expf(-accA[mf][nf][3])));
                *(float2*)(g_ogate + (pbase+row)*128 + col)   = p0;
                *(float2*)(g_ogate + (pbase+row+8)*128 + col) = p1;
            }
    }
}

// ---------------- Stage B: per-channel bf16 einsum (ldmatrix) ----------------
__device__ __forceinline__ void cpa16(void* dst, const void* src) {
    unsigned u = (unsigned)__cvta_generic_to_shared(dst);
    asm volatile("cp.async.cg.shared.global [%0], [%1], 16;\n" :: "r"(u), "l"(src) : "memory");
}
__device__ __forceinline__ void sb_issue(const __nv_bfloat16* gA, const __nv_bfloat16* gB,
                                         __nv_bfloat16* sA, __nv_bfloat16* sB, int tid, int k0) {
    #pragma unroll
    for (int q = 0; q < 2; q++) {
        int idx = tid + 256*q, row = idx >> 2, seg = (idx & 3) << 3;
        cpa16(sA + row*40 + seg, gA + (size_t)row*NN + k0 + seg);
        cpa16(sB + row*40 + seg, gB + (size_t)row*NN + k0 + seg);
    }
    asm volatile("cp.async.commit_group;\n" ::: "memory");
}

__global__ __launch_bounds__(256, 2) void stage_b() {
    __shared__ __align__(16) __nv_bfloat16 smb[4*128*40];
    __nv_bfloat16* sA = smb;
    __nv_bfloat16* sB = smb + 2*128*40;

    const int tid = threadIdx.x, lane = tid & 31, warp = tid >> 5;
    const int wm = warp & 1, wn = warp >> 1;
    const int d = blockIdx.y, ti = blockIdx.x / 6, tj = blockIdx.x % 6;
    const __nv_bfloat16* gA = g_left  + (size_t)d*PP + (size_t)(ti*128)*NN;
    const __nv_bfloat16* gB = g_right + (size_t)d*PP + (size_t)(tj*128)*NN;

    const int lr  = lane & 15, lkA = (lane >> 4) << 3;
    const int bn  = lane & 7, bks = ((lane >> 3) & 1) << 3;
    const int bnf = lane >> 4;

    float c[4][4][4] = {};
    sb_issue(gA, gB, sA, sB, tid, 0);

    #pragma unroll 1
    for (int kt = 0; kt < 24; kt++) {
        int buf = kt & 1;
        if (kt < 23) {
            sb_issue(gA, gB, sA + (buf^1)*5120, sB + (buf^1)*5120, tid, (kt+1)*32);
            asm volatile("cp.async.wait_group 1;\n" ::: "memory");
        } else {
            asm volatile("cp.async.wait_group 0;\n" ::: "memory");
        }
        __syncthreads();
        const __nv_bfloat16* Ab = sA + buf*5120;
        const __nv_bfloat16* Bb = sB + buf*5120;
        #pragma unroll
        for (int kk = 0; kk < 2; kk++) {
            uint32_t a[4][4], b[4][2];
            #pragma unroll
            for (int fm = 0; fm < 4; fm++)
                ldsm4(a[fm], Ab + (wm*64 + fm*16 + lr)*40 + kk*16 + lkA);
            #pragma unroll
            for (int nf = 0; nf < 4; nf += 2) {
                uint32_t t[4];
                ldsm4(t, Bb + (wn*32 + (nf + bnf)*8 + bn)*40 + kk*16 + bks);
                b[nf][0]=t[0]; b[nf][1]=t[1]; b[nf+1][0]=t[2]; b[nf+1][1]=t[3];
            }
            #pragma unroll
            for (int fm = 0; fm < 4; fm++)
                #pragma unroll
                for (int fn = 0; fn < 4; fn++) mma16816(c[fm][fn], a[fm], b[fn]);
        }
        __syncthreads();
    }

    __nv_bfloat16* gO = g_pair + (size_t)d*PP;
    #pragma unroll
    for (int fm = 0; fm < 4; fm++)
        #pragma unroll
        for (int fn = 0; fn < 4; fn++) {
            int r0 = ti*128 + wm*64 + fm*16 + (lane >> 2);
            int cc = tj*128 + wn*32 + fn*8 + (lane & 3)*2;
            *(__nv_bfloat162*)(gO + (size_t)r0*NN + cc) =
                __float22bfloat162_rn(make_float2(c[fm][fn][0], c[fm][fn][1]));
            *(__nv_bfloat162*)(gO + (size_t)(r0+8)*NN + cc) =
                __float22bfloat162_rn(make_float2(c[fm][fn][2], c[fm][fn][3]));
        }
}

// ------ Stage C (mma): LN over H + out_gate + final projection, M=64 ------
#define SC_SMEM (2*17408 + 2*34816)   // 102 KB -> 2 CTAs/SM

__global__ __launch_bounds__(256, 2) void stage_cmm(
    const float* __restrict__ onw, const float* __restrict__ onb,
    const float* __restrict__ wout, float* __restrict__ out)
{
    extern __shared__ __nv_bfloat16 smc[];
    __nv_bfloat16* s_vh = smc;            // [64 pos][136]
    __nv_bfloat16* s_vl = smc + 8704;
    __nv_bfloat16* s_wh = smc + 17408;    // [128 dout][136]
    __nv_bfloat16* s_wl = smc + 34816;
    __nv_bfloat16* s_t  = s_wh;           // [128 d][68] overlay, dead before w fill

    const int tid = threadIdx.x, lane = tid & 31, warp = tid >> 5;
    const int wm = warp & 1, wn = warp >> 1;
    const size_t p0 = (size_t)blockIdx.x * 64;

    #pragma unroll
    for (int q = 0; q < 8; q++) { // pair tile [128 d][64 pos]
        int idx = tid + 256*q, dd = idx >> 4, seg = (idx & 15) << 2;
        *(uint2*)(s_t + dd*68 + seg) = *(const uint2*)(g_pair + (size_t)dd*PP + p0 + seg);
    }
    __syncthreads();

    float lw[4], lb[4];
    #pragma unroll
    for (int q = 0; q < 4; q++) { lw[q] = onw[lane+32*q]; lb[q] = onb[lane+32*q]; }

    #pragma unroll 1
    for (int pp = 0; pp < 8; pp++) { // LN over d + gate, warp per position
        int pos = warp*8 + pp;
        float t[4];
        #pragma unroll
        for (int q = 0; q < 4; q++) t[q] = __bfloat162float(s_t[(lane+32*q)*68 + pos]);
        float s = t[0]+t[1]+t[2]+t[3];
        float sq = t[0]*t[0]+t[1]*t[1]+t[2]*t[2]+t[3]*t[3];
        #pragma unroll
        for (int o = 16; o; o >>= 1) {
            s  += __shfl_xor_sync(~0u, s,  o);
            sq += __shfl_xor_sync(~0u, sq, o);
        }
        float mu = s*(1.f/128.f), var = sq*(1.f/128.f) - mu*mu;
        float rstd = rsqrtf(var + 1e-5f);
        #pragma unroll
        for (int q = 0; q < 4; q++) {
            float v = (t[q]-mu)*rstd*lw[q] + lb[q];
            v *= g_ogate[(p0+pos)*128 + lane + 32*q];
            __nv_bfloat16 h = __float2bfloat16_rn(v);
            s_vh[pos*136 + lane + 32*q] = h;
            s_vl[pos*136 + lane + 32*q] = __float2bfloat16_rn(v - __bfloat162float(h));
        }
    }
    __syncthreads();  // LN reads of s_t done; safe to overwrite with w_out

    split_w128(wout, s_wh, s_wl, tid);
    __syncthreads();

    float acc[2][4][4] = {};
    gemm_tile_t<4>(acc, s_vh, s_vl, s_wh, s_wl, lane, wm*32, wn*32);

    #pragma unroll
    for (int mf = 0; mf < 2; mf++)
        #pragma unroll
        for (int nf = 0; nf < 4; nf++) {
            int row = wm*32 + mf*16 + (lane >> 2);
            int col = wn*32 + nf*8 + (lane & 3)*2;
            *(float2*)(out + (p0+row)*128 + col)   = make_float2(acc[mf][nf][0], acc[mf][nf][1]);
            *(float2*)(out + (p0+row+8)*128 + col) = make_float2(acc[mf][nf][2], acc[mf][nf][3]);
        }
}

// -----------------------------------------------------------------------------
extern "C" void kernel_launch(void* const* d_in, const int* in_sizes, int n_in,
                              void* d_out, int out_size) {
    (void)in_sizes; (void)n_in; (void)out_size;
    const float* x    = (const float*)d_in[0];
    const float* mask = (const float*)d_in[1];
    const float* nw   = (const float*)d_in[2];
    const float* nb   = (const float*)d_in[3];
    const float* wl   = (const float*)d_in[4];
    const float* wr   = (const float*)d_in[5];
    const float* wlg  = (const float*)d_in[6];
    const float* wrg  = (const float*)d_in[7];
    const float* wog  = (const float*)d_in[8];
    const float* onw  = (const float*)d_in[9];
    const float* onb  = (const float*)d_in[10];
    const float* wout = (const float*)d_in[11];
    float* out = (float*)d_out;

    cudaFuncSetAttribute(stage_amm, cudaFuncAttributeMaxDynamicSharedMemorySize, AM_SMEM);
    cudaFuncSetAttribute(stage_cmm, cudaFuncAttributeMaxDynamicSharedMemorySize, SC_SMEM);

    stage_ln<<<PP/64, 256>>>(x, nw, nb);
    stage_amm<<<dim3(PP/64, 3), 256, AM_SMEM>>>(mask, wl, wr, wlg, wrg, wog);
    stage_b<<<dim3(36, 128), 256>>>();
    stage_cmm<<<PP/64, 256, SC_SMEM>>>(onw, onb, wout, out);
}

// round 11
// speedup vs baseline: 2.2756x; 1.0651x over previous
#include <cuda_runtime.h>
#include <cuda_bf16.h>
#include <cstdint>

#define NN 768
#define PP (NN*NN)

__device__ __align__(256) __nv_bfloat16 g_left [(size_t)128 * PP]; // [h][i*N+k]
__device__ __align__(256) __nv_bfloat16 g_right[(size_t)128 * PP]; // [h][j*N+k]
__device__ __align__(256) __nv_bfloat16 g_pair [(size_t)128 * PP]; // [d][i*N+j]
__device__ __align__(256) float         g_ogate[(size_t)PP  * 128]; // [p][h]

// ---------------- mma helpers ----------------
__device__ __forceinline__ void mma16816(float* c, const uint32_t* a, const uint32_t* b) {
    asm volatile("mma.sync.aligned.m16n8k16.row.col.f32.bf16.bf16.f32 "
                 "{%0,%1,%2,%3}, {%4,%5,%6,%7}, {%8,%9}, {%0,%1,%2,%3};\n"
                 : "+f"(c[0]), "+f"(c[1]), "+f"(c[2]), "+f"(c[3])
                 : "r"(a[0]), "r"(a[1]), "r"(a[2]), "r"(a[3]), "r"(b[0]), "r"(b[1]));
}
__device__ __forceinline__ void ldsm4(uint32_t* r, const void* p) {
    unsigned a = (unsigned)__cvta_generic_to_shared(p);
    asm volatile("ldmatrix.sync.aligned.m8n8.x4.shared.b16 {%0,%1,%2,%3}, [%4];\n"
                 : "=r"(r[0]), "=r"(r[1]), "=r"(r[2]), "=r"(r[3]) : "r"(a));
}

// M(2x16) x N(NF x 8) x K128 split-bf16 GEMM tile: acc += X * W^T.
// 3 passes: hi*hi, hi*lo, lo*hi (lo*lo ~2^-18, dropped). Pitch = 136 bf16.
template<int NF>
__device__ __forceinline__ void gemm_tile_t(
    float (&acc)[2][NF][4],
    const __nv_bfloat16* sXh, const __nv_bfloat16* sXl,
    const __nv_bfloat16* sWh, const __nv_bfloat16* sWl,
    int lane, int mbase, int nbase)
{
    const int lr  = lane & 15, lkA = (lane >> 4) << 3;       // A ldsm addressing
    const int bn  = lane & 7, bks = ((lane >> 3) & 1) << 3;  // B ldsm addressing
    const int bnf = lane >> 4;
    #pragma unroll 1
    for (int pass = 0; pass < 3; pass++) {
        const __nv_bfloat16* X = (pass == 2) ? sXl : sXh;
        const __nv_bfloat16* W = (pass == 1) ? sWl : sWh;
        #pragma unroll
        for (int ks = 0; ks < 8; ks++) {
            uint32_t a[2][4], b[NF][2];
            #pragma unroll
            for (int mf = 0; mf < 2; mf++)
                ldsm4(a[mf], X + (mbase + mf*16 + lr)*136 + ks*16 + lkA);
            #pragma unroll
            for (int nf = 0; nf < NF; nf += 2) {
                uint32_t t[4];
                ldsm4(t, W + (nbase + (nf + bnf)*8 + bn)*136 + ks*16 + bks);
                b[nf][0]=t[0]; b[nf][1]=t[1]; b[nf+1][0]=t[2]; b[nf+1][1]=t[3];
            }
            #pragma unroll
            for (int mf = 0; mf < 2; mf++)
                #pragma unroll
                for (int nf = 0; nf < NF; nf++)
                    mma16816(acc[mf][nf], a[mf], b[nf]);
        }
    }
}

// split a [128][128] fp32 weight matrix into bf16 hi/lo smem tiles, pitch 136
__device__ __forceinline__ void split_w128(const float* __restrict__ W,
                                           __nv_bfloat16* sh, __nv_bfloat16* sl, int tid) {
    #pragma unroll
    for (int q = 0; q < 16; q++) {
        int idx = tid + 256*q, row = idx >> 5, c4 = (idx & 31) << 2;
        float4 w = *(const float4*)(W + (size_t)row*128 + c4);
        __nv_bfloat16 hx=__float2bfloat16_rn(w.x), hy=__float2bfloat16_rn(w.y);
        __nv_bfloat16 hz=__float2bfloat16_rn(w.z), hw=__float2bfloat16_rn(w.w);
        __nv_bfloat162 hp0; hp0.x=hx; hp0.y=hy;
        __nv_bfloat162 hp1; hp1.x=hz; hp1.y=hw;
        __nv_bfloat162 lp0 = __floats2bfloat162_rn(w.x-__bfloat162float(hx), w.y-__bfloat162float(hy));
        __nv_bfloat162 lp1 = __floats2bfloat162_rn(w.z-__bfloat162float(hz), w.w-__bfloat162float(hw));
        *(__nv_bfloat162*)(sh + row*136 + c4)     = hp0;
        *(__nv_bfloat162*)(sh + row*136 + c4 + 2) = hp1;
        *(__nv_bfloat162*)(sl + row*136 + c4)     = lp0;
        *(__nv_bfloat162*)(sl + row*136 + c4 + 2) = lp1;
    }
}

// ---- Stage A fused: LN + 5 projections + gating, X resident, M=64 ----
#define AM_SMEM (2*17408 + 2*34816)   // 102 KB -> 2 CTAs/SM

__global__ __launch_bounds__(256, 2) void stage_a_fused(
    const float* __restrict__ x,   const float* __restrict__ mask,
    const float* __restrict__ nw,  const float* __restrict__ nb,
    const float* __restrict__ wl,  const float* __restrict__ wr,
    const float* __restrict__ wlg, const float* __restrict__ wrg,
    const float* __restrict__ wog)
{
    extern __shared__ __nv_bfloat16 smem[];
    __nv_bfloat16* sXh = smem;            // [64][136]  (live whole kernel)
    __nv_bfloat16* sXl = smem + 8704;
    __nv_bfloat16* sWh = smem + 17408;    // [128][136] (recycled per weight)
    __nv_bfloat16* sWl = smem + 34816;

    const int tid = threadIdx.x, lane = tid & 31, warp = tid >> 5;
    const int wm = warp & 1, wn = warp >> 1;
    const size_t pbase = (size_t)blockIdx.x * 64;

    { // LayerNorm straight from gmem into sXh/sXl, warp per position
        float4 w4 = ((const float4*)nw)[lane], b4 = ((const float4*)nb)[lane];
        #pragma unroll 1
        for (int pp = 0; pp < 8; pp++) {
            int pos = warp*8 + pp;
            float4 v = ((const float4*)(x + (pbase+pos)*128))[lane];
            float s  = v.x+v.y+v.z+v.w;
            float sq = v.x*v.x+v.y*v.y+v.z*v.z+v.w*v.w;
            #pragma unroll
            for (int o = 16; o; o >>= 1) {
                s  += __shfl_xor_sync(~0u, s,  o);
                sq += __shfl_xor_sync(~0u, sq, o);
            }
            float mu = s*(1.f/128.f), var = sq*(1.f/128.f) - mu*mu;
            float rstd = rsqrtf(var + 1e-5f);
            v.x=(v.x-mu)*rstd*w4.x+b4.x; v.y=(v.y-mu)*rstd*w4.y+b4.y;
            v.z=(v.z-mu)*rstd*w4.z+b4.z; v.w=(v.w-mu)*rstd*w4.w+b4.w;
            __nv_bfloat16 hx=__float2bfloat16_rn(v.x), hy=__float2bfloat16_rn(v.y);
            __nv_bfloat16 hz=__float2bfloat16_rn(v.z), hw=__float2bfloat16_rn(v.w);
            __nv_bfloat162 h01; h01.x=hx; h01.y=hy;
            __nv_bfloat162 h23; h23.x=hz; h23.y=hw;
            __nv_bfloat162 l01 = __floats2bfloat162_rn(v.x-__bfloat162float(hx), v.y-__bfloat162float(hy));
            __nv_bfloat162 l23 = __floats2bfloat162_rn(v.z-__bfloat162float(hz), v.w-__bfloat162float(hw));
            *(__nv_bfloat162*)(sXh + pos*136 + lane*4)     = h01;
            *(__nv_bfloat162*)(sXh + pos*136 + lane*4 + 2) = h23;
            *(__nv_bfloat162*)(sXl + pos*136 + lane*4)     = l01;
            *(__nv_bfloat162*)(sXl + pos*136 + lane*4 + 2) = l23;
        }
    }

    float mrow[2][2];
    #pragma unroll
    for (int mf = 0; mf < 2; mf++) {
        int r = wm*32 + mf*16 + (lane >> 2);
        mrow[mf][0] = mask[pbase + r];
        mrow[mf][1] = mask[pbase + r + 8];
    }

    #pragma unroll 1
    for (int mat = 0; mat < 3; mat++) {
        const bool dual = (mat < 2);
        const float* WA = (mat==0) ? wl : (mat==1) ? wr : wog;
        const float* WB = (mat==0) ? wlg : wrg;

        __syncthreads();                 // X ready (mat 0) / prior epilogue reads done
        split_w128(WA, sWh, sWl, tid);
        __syncthreads();
        float accA[2][4][4] = {};
        gemm_tile_t<4>(accA, sXh, sXl, sWh, sWl, lane, wm*32, wn*32);

        if (dual) {
            __syncthreads();             // WA reads done
            split_w128(WB, sWh, sWl, tid);
            __syncthreads();
            float accB[2][4][4] = {};
            gemm_tile_t<4>(accB, sXh, sXl, sWh, sWl, lane, wm*32, wn*32);

            __nv_bfloat16* s_stage = sWh;  // [128 h][68 pos], W dead after gemms
            __syncthreads();
            #pragma unroll
            for (int mf = 0; mf < 2; mf++)
                #pragma unroll
                for (int nf = 0; nf < 4; nf++) {
                    int row = wm*32 + mf*16 + (lane >> 2);
                    int col = wn*32 + nf*8 + (lane & 3)*2;
                    float g0 = 1.f/(1.f+__expf(-accB[mf][nf][0]));
                    float g1 = 1.f/(1.f+__expf(-accB[mf][nf][1]));
                    float g2 = 1.f/(1.f+__expf(-accB[mf][nf][2]));
                    float g3 = 1.f/(1.f+__expf(-accB[mf][nf][3]));
                    s_stage[ col   *68 + row  ] = __float2bfloat16(accA[mf][nf][0]*mrow[mf][0]*g0);
                    s_stage[(col+1)*68 + row  ] = __float2bfloat16(accA[mf][nf][1]*mrow[mf][0]*g1);
                    s_stage[ col   *68 + row+8] = __float2bfloat16(accA[mf][nf][2]*mrow[mf][1]*g2);
                    s_stage[(col+1)*68 + row+8] = __float2bfloat16(accA[mf][nf][3]*mrow[mf][1]*g3);
                }
            __syncthreads();
            __nv_bfloat16* gdst = (mat == 0) ? g_left : g_right;
            #pragma unroll
            for (int q = 0; q < 8; q++) {
                int idx = tid + 256*q, hh = idx >> 4, seg = (idx & 15) << 2;
                *(uint2*)(gdst + (size_t)hh*PP + pbase + seg) =
                    *(const uint2*)(s_stage + hh*68 + seg);
            }
        } else {
            #pragma unroll
            for (int mf = 0; mf < 2; mf++)
                #pragma unroll
                for (int nf = 0; nf < 4; nf++) {
                    int row = wm*32 + mf*16 + (lane >> 2);
                    int col = wn*32 + nf*8 + (lane & 3)*2;
                    float2 p0 = make_float2(1.f/(1.f+__expf(-accA[mf][nf][0])),
                                            1.f/(1.f+__expf(-accA[mf][nf][1])));
                    float2 p1 = make_float2(1.f/(1.f+__expf(-accA[mf][nf][2])),
                                            1.f/(1.f+__expf(-accA[mf][nf][3])));
                    *(float2*)(g_ogate + (pbase+row)*128 + col)   = p0;
                    *(float2*)(g_ogate + (pbase+row+8)*128 + col) = p1;
                }
        }
    }
}

// -------- Stage B: per-channel bf16 einsum, k-chunk 64, ldmatrix --------
#define SB_SMEM (4*128*72*2)   // 73728 B -> 2 CTAs/SM

__device__ __forceinline__ void cpa16(void* dst, const void* src) {
    unsigned u = (unsigned)__cvta_generic_to_shared(dst);
    asm volatile("cp.async.cg.shared.global [%0], [%1], 16;\n" :: "r"(u), "l"(src) : "memory");
}
__device__ __forceinline__ void sb_issue(const __nv_bfloat16* gA, const __nv_bfloat16* gB,
                                         __nv_bfloat16* sA, __nv_bfloat16* sB, int tid, int k0) {
    #pragma unroll
    for (int q = 0; q < 4; q++) {
        int idx = tid + 256*q, row = idx >> 3, seg = (idx & 7) << 3;
        cpa16(sA + row*72 + seg, gA + (size_t)row*NN + k0 + seg);
        cpa16(sB + row*72 + seg, gB + (size_t)row*NN + k0 + seg);
    }
    asm volatile("cp.async.commit_group;\n" ::: "memory");
}

__global__ __launch_bounds__(256, 2) void stage_b() {
    extern __shared__ __nv_bfloat16 smb[];
    __nv_bfloat16* sA = smb;              // [2 buf][128][72]
    __nv_bfloat16* sB = smb + 2*128*72;

    const int tid = threadIdx.x, lane = tid & 31, warp = tid >> 5;
    const int wm = warp & 1, wn = warp >> 1;
    const int d = blockIdx.y, ti = blockIdx.x / 6, tj = blockIdx.x % 6;
    const __nv_bfloat16* gA = g_left  + (size_t)d*PP + (size_t)(ti*128)*NN;
    const __nv_bfloat16* gB = g_right + (size_t)d*PP + (size_t)(tj*128)*NN;

    const int lr  = lane & 15, lkA = (lane >> 4) << 3;
    const int bn  = lane & 7, bks = ((lane >> 3) & 1) << 3;
    const int bnf = lane >> 4;

    float c[4][4][4] = {};
    sb_issue(gA, gB, sA, sB, tid, 0);

    #pragma unroll 1
    for (int kt = 0; kt < 12; kt++) {
        int buf = kt & 1;
        if (kt < 11) {
            sb_issue(gA, gB, sA + (buf^1)*9216, sB + (buf^1)*9216, tid, (kt+1)*64);
            asm volatile("cp.async.wait_group 1;\n" ::: "memory");
        } else {
            asm volatile("cp.async.wait_group 0;\n" ::: "memory");
        }
        __syncthreads();
        const __nv_bfloat16* Ab = sA + buf*9216;
        const __nv_bfloat16* Bb = sB + buf*9216;
        #pragma unroll
        for (int kk = 0; kk < 4; kk++) {
            uint32_t a[4][4], b[4][2];
            #pragma unroll
            for (int fm = 0; fm < 4; fm++)
                ldsm4(a[fm], Ab + (wm*64 + fm*16 + lr)*72 + kk*16 + lkA);
            #pragma unroll
            for (int nf = 0; nf < 4; nf += 2) {
                uint32_t t[4];
                ldsm4(t, Bb + (wn*32 + (nf + bnf)*8 + bn)*72 + kk*16 + bks);
                b[nf][0]=t[0]; b[nf][1]=t[1]; b[nf+1][0]=t[2]; b[nf+1][1]=t[3];
            }
            #pragma unroll
            for (int fm = 0; fm < 4; fm++)
                #pragma unroll
                for (int fn = 0; fn < 4; fn++) mma16816(c[fm][fn], a[fm], b[fn]);
        }
        __syncthreads();
    }

    __nv_bfloat16* gO = g_pair + (size_t)d*PP;
    #pragma unroll
    for (int fm = 0; fm < 4; fm++)
        #pragma unroll
        for (int fn = 0; fn < 4; fn++) {
            int r0 = ti*128 + wm*64 + fm*16 + (lane >> 2);
            int cc = tj*128 + wn*32 + fn*8 + (lane & 3)*2;
            *(__nv_bfloat162*)(gO + (size_t)r0*NN + cc) =
                __float22bfloat162_rn(make_float2(c[fm][fn][0], c[fm][fn][1]));
            *(__nv_bfloat162*)(gO + (size_t)(r0+8)*NN + cc) =
                __float22bfloat162_rn(make_float2(c[fm][fn][2], c[fm][fn][3]));
        }
}

// ------ Stage C (mma): LN over H + out_gate + final projection, M=64 ------
#define SC_SMEM (2*17408 + 2*34816)   // 102 KB -> 2 CTAs/SM

__global__ __launch_bounds__(256, 2) void stage_cmm(
    const float* __restrict__ onw, const float* __restrict__ onb,
    const float* __restrict__ wout, float* __restrict__ out)
{
    extern __shared__ __nv_bfloat16 smc[];
    __nv_bfloat16* s_vh = smc;            // [64 pos][136]
    __nv_bfloat16* s_vl = smc + 8704;
    __nv_bfloat16* s_wh = smc + 17408;    // [128 dout][136]
    __nv_bfloat16* s_wl = smc + 34816;
    __nv_bfloat16* s_t  = s_wh;           // [128 d][68] overlay, dead before w fill

    const int tid = threadIdx.x, lane = tid & 31, warp = tid >> 5;
    const int wm = warp & 1, wn = warp >> 1;
    const size_t p0 = (size_t)blockIdx.x * 64;

    #pragma unroll
    for (int q = 0; q < 8; q++) { // pair tile [128 d][64 pos]
        int idx = tid + 256*q, dd = idx >> 4, seg = (idx & 15) << 2;
        *(uint2*)(s_t + dd*68 + seg) = *(const uint2*)(g_pair + (size_t)dd*PP + p0 + seg);
    }
    __syncthreads();

    float lw[4], lb[4];
    #pragma unroll
    for (int q = 0; q < 4; q++) { lw[q] = onw[lane+32*q]; lb[q] = onb[lane+32*q]; }

    #pragma unroll 1
    for (int pp = 0; pp < 8; pp++) { // LN over d + gate, warp per position
        int pos = warp*8 + pp;
        float t[4];
        #pragma unroll
        for (int q = 0; q < 4; q++) t[q] = __bfloat162float(s_t[(lane+32*q)*68 + pos]);
        float s = t[0]+t[1]+t[2]+t[3];
        float sq = t[0]*t[0]+t[1]*t[1]+t[2]*t[2]+t[3]*t[3];
        #pragma unroll
        for (int o = 16; o; o >>= 1) {
            s  += __shfl_xor_sync(~0u, s,  o);
            sq += __shfl_xor_sync(~0u, sq, o);
        }
        float mu = s*(1.f/128.f), var = sq*(1.f/128.f) - mu*mu;
        float rstd = rsqrtf(var + 1e-5f);
        #pragma unroll
        for (int q = 0; q < 4; q++) {
            float v = (t[q]-mu)*rstd*lw[q] + lb[q];
            v *= g_ogate[(p0+pos)*128 + lane + 32*q];
            __nv_bfloat16 h = __float2bfloat16_rn(v);
            s_vh[pos*136 + lane + 32*q] = h;
            s_vl[pos*136 + lane + 32*q] = __float2bfloat16_rn(v - __bfloat162float(h));
        }
    }
    __syncthreads();  // LN reads of s_t done; safe to overwrite with w_out

    split_w128(wout, s_wh, s_wl, tid);
    __syncthreads();

    float acc[2][4][4] = {};
    gemm_tile_t<4>(acc, s_vh, s_vl, s_wh, s_wl, lane, wm*32, wn*32);

    #pragma unroll
    for (int mf = 0; mf < 2; mf++)
        #pragma unroll
        for (int nf = 0; nf < 4; nf++) {
            int row = wm*32 + mf*16 + (lane >> 2);
            int col = wn*32 + nf*8 + (lane & 3)*2;
            *(float2*)(out + (p0+row)*128 + col)   = make_float2(acc[mf][nf][0], acc[mf][nf][1]);
            *(float2*)(out + (p0+row+8)*128 + col) = make_float2(acc[mf][nf][2], acc[mf][nf][3]);
        }
}

// -----------------------------------------------------------------------------
extern "C" void kernel_launch(void* const* d_in, const int* in_sizes, int n_in,
                              void* d_out, int out_size) {
    (void)in_sizes; (void)n_in; (void)out_size;
    const float* x    = (const float*)d_in[0];
    const float* mask = (const float*)d_in[1];
    const float* nw   = (const float*)d_in[2];
    const float* nb   = (const float*)d_in[3];
    const float* wl   = (const float*)d_in[4];
    const float* wr   = (const float*)d_in[5];
    const float* wlg  = (const float*)d_in[6];
    const float* wrg  = (const float*)d_in[7];
    const float* wog  = (const float*)d_in[8];
    const float* onw  = (const float*)d_in[9];
    const float* onb  = (const float*)d_in[10];
    const float* wout = (const float*)d_in[11];
    float* out = (float*)d_out;

    cudaFuncSetAttribute(stage_a_fused, cudaFuncAttributeMaxDynamicSharedMemorySize, AM_SMEM);
    cudaFuncSetAttribute(stage_b,       cudaFuncAttributeMaxDynamicSharedMemorySize, SB_SMEM);
    cudaFuncSetAttribute(stage_cmm,     cudaFuncAttributeMaxDynamicSharedMemorySize, SC_SMEM);

    stage_a_fused<<<PP/64, 256, AM_SMEM>>>(x, mask, nw, nb, wl, wr, wlg, wrg, wog);
    stage_b<<<dim3(36, 128), 256, SB_SMEM>>>();
    stage_cmm<<<PP/64, 256, SC_SMEM>>>(onw, onb, wout, out);
}

// round 12
// speedup vs baseline: 2.4087x; 1.0585x over previous
#include <cuda_runtime.h>
#include <cuda_bf16.h>
#include <cstdint>

#define NN 768
#define PP (NN*NN)

__device__ __align__(256) __nv_bfloat16 g_left [(size_t)128 * PP]; // [h][i*N+k]
__device__ __align__(256) __nv_bfloat16 g_right[(size_t)128 * PP]; // [h][j*N+k]
__device__ __align__(256) __nv_bfloat16 g_pair [(size_t)128 * PP]; // [d][i*N+j]
__device__ __align__(256) float         g_ogate[(size_t)PP  * 128]; // [p][h]
__device__ __align__(256) __nv_bfloat16 g_wh[6][128*128];           // weight hi
__device__ __align__(256) __nv_bfloat16 g_wlo[6][128*128];          // weight lo

// ---------------- mma helpers ----------------
__device__ __forceinline__ void mma16816(float* c, const uint32_t* a, const uint32_t* b) {
    asm volatile("mma.sync.aligned.m16n8k16.row.col.f32.bf16.bf16.f32 "
                 "{%0,%1,%2,%3}, {%4,%5,%6,%7}, {%8,%9}, {%0,%1,%2,%3};\n"
                 : "+f"(c[0]), "+f"(c[1]), "+f"(c[2]), "+f"(c[3])
                 : "r"(a[0]), "r"(a[1]), "r"(a[2]), "r"(a[3]), "r"(b[0]), "r"(b[1]));
}
__device__ __forceinline__ void ldsm4(uint32_t* r, const void* p) {
    unsigned a = (unsigned)__cvta_generic_to_shared(p);
    asm volatile("ldmatrix.sync.aligned.m8n8.x4.shared.b16 {%0,%1,%2,%3}, [%4];\n"
                 : "=r"(r[0]), "=r"(r[1]), "=r"(r[2]), "=r"(r[3]) : "r"(a));
}

// M(2x16) x N(NF x 8) x K128 split-bf16 GEMM: acc += X*W^T.
// Fused 3 passes (hh, hl, lh) per k-step: fragments loaded once, 3 mma each.
template<int NF>
__device__ __forceinline__ void gemm_tile3(
    float (&acc)[2][NF][4],
    const __nv_bfloat16* sXh, const __nv_bfloat16* sXl,
    const __nv_bfloat16* sWh, const __nv_bfloat16* sWl,
    int lane, int mbase, int nbase)
{
    const int lr  = lane & 15, lkA = (lane >> 4) << 3;
    const int bn  = lane & 7, bks = ((lane >> 3) & 1) << 3;
    const int bnf = lane >> 4;
    #pragma unroll
    for (int ks = 0; ks < 8; ks++) {
        uint32_t ah[2][4], al[2][4], bh[NF][2], bl[NF][2];
        #pragma unroll
        for (int mf = 0; mf < 2; mf++) {
            ldsm4(ah[mf], sXh + (mbase + mf*16 + lr)*136 + ks*16 + lkA);
            ldsm4(al[mf], sXl + (mbase + mf*16 + lr)*136 + ks*16 + lkA);
        }
        #pragma unroll
        for (int nf = 0; nf < NF; nf += 2) {
            uint32_t t[4];
            ldsm4(t, sWh + (nbase + (nf + bnf)*8 + bn)*136 + ks*16 + bks);
            bh[nf][0]=t[0]; bh[nf][1]=t[1]; bh[nf+1][0]=t[2]; bh[nf+1][1]=t[3];
            ldsm4(t, sWl + (nbase + (nf + bnf)*8 + bn)*136 + ks*16 + bks);
            bl[nf][0]=t[0]; bl[nf][1]=t[1]; bl[nf+1][0]=t[2]; bl[nf+1][1]=t[3];
        }
        #pragma unroll
        for (int mf = 0; mf < 2; mf++)
            #pragma unroll
            for (int nf = 0; nf < NF; nf++) {
                mma16816(acc[mf][nf], ah[mf], bh[nf]);
                mma16816(acc[mf][nf], ah[mf], bl[nf]);
                mma16816(acc[mf][nf], al[mf], bh[nf]);
            }
    }
}

// ---------------- Stage Wsplit: split 6 weight mats to bf16 hi/lo ----------------
__global__ void stage_wsplit(
    const float* __restrict__ wl, const float* __restrict__ wr,
    const float* __restrict__ wlg, const float* __restrict__ wrg,
    const float* __restrict__ wog, const float* __restrict__ wout)
{
    const float* Ws[6] = {wl, wr, wlg, wrg, wog, wout};
    const float* W = Ws[blockIdx.x];
    __nv_bfloat16* gh = g_wh[blockIdx.x];
    __nv_bfloat16* gl = g_wlo[blockIdx.x];
    for (int i = threadIdx.x; i < 128*128/2; i += 256) {
        float2 w = ((const float2*)W)[i];
        __nv_bfloat16 hx = __float2bfloat16_rn(w.x), hy = __float2bfloat16_rn(w.y);
        __nv_bfloat162 hp; hp.x = hx; hp.y = hy;
        ((__nv_bfloat162*)gh)[i] = hp;
        ((__nv_bfloat162*)gl)[i] =
            __floats2bfloat162_rn(w.x - __bfloat162float(hx), w.y - __bfloat162float(hy));
    }
}

// copy pre-split [128][128] weight hi/lo into smem tiles, pitch 136
__device__ __forceinline__ void copy_w128(const __nv_bfloat16* __restrict__ gh,
                                          const __nv_bfloat16* __restrict__ gl,
                                          __nv_bfloat16* sh, __nv_bfloat16* sl, int tid) {
    #pragma unroll
    for (int q = 0; q < 8; q++) {
        int idx = tid + 256*q, row = idx >> 4, seg = (idx & 15) << 3;
        *(uint4*)(sh + row*136 + seg) = *(const uint4*)(gh + row*128 + seg);
        *(uint4*)(sl + row*136 + seg) = *(const uint4*)(gl + row*128 + seg);
    }
}

// ---- Stage A fused: LN + 5 projections + gating, X resident, M=64 ----
#define AM_SMEM (2*17408 + 2*34816)   // 102 KB -> 2 CTAs/SM

__global__ __launch_bounds__(256, 2) void stage_a_fused(
    const float* __restrict__ x,   const float* __restrict__ mask,
    const float* __restrict__ nw,  const float* __restrict__ nb)
{
    extern __shared__ __nv_bfloat16 smem[];
    __nv_bfloat16* sXh = smem;            // [64][136]  (live whole kernel)
    __nv_bfloat16* sXl = smem + 8704;
    __nv_bfloat16* sWh = smem + 17408;    // [128][136] (recycled per weight)
    __nv_bfloat16* sWl = smem + 34816;

    const int tid = threadIdx.x, lane = tid & 31, warp = tid >> 5;
    const int wm = warp & 1, wn = warp >> 1;
    const size_t pbase = (size_t)blockIdx.x * 64;

    { // LayerNorm straight from gmem into sXh/sXl, warp per position
        float4 w4 = ((const float4*)nw)[lane], b4 = ((const float4*)nb)[lane];
        #pragma unroll 1
        for (int pp = 0; pp < 8; pp++) {
            int pos = warp*8 + pp;
            float4 v = ((const float4*)(x + (pbase+pos)*128))[lane];
            float s  = v.x+v.y+v.z+v.w;
            float sq = v.x*v.x+v.y*v.y+v.z*v.z+v.w*v.w;
            #pragma unroll
            for (int o = 16; o; o >>= 1) {
                s  += __shfl_xor_sync(~0u, s,  o);
                sq += __shfl_xor_sync(~0u, sq, o);
            }
            float mu = s*(1.f/128.f), var = sq*(1.f/128.f) - mu*mu;
            float rstd = rsqrtf(var + 1e-5f);
            v.x=(v.x-mu)*rstd*w4.x+b4.x; v.y=(v.y-mu)*rstd*w4.y+b4.y;
            v.z=(v.z-mu)*rstd*w4.z+b4.z; v.w=(v.w-mu)*rstd*w4.w+b4.w;
            __nv_bfloat16 hx=__float2bfloat16_rn(v.x), hy=__float2bfloat16_rn(v.y);
            __nv_bfloat16 hz=__float2bfloat16_rn(v.z), hw=__float2bfloat16_rn(v.w);
            __nv_bfloat162 h01; h01.x=hx; h01.y=hy;
            __nv_bfloat162 h23; h23.x=hz; h23.y=hw;
            __nv_bfloat162 l01 = __floats2bfloat162_rn(v.x-__bfloat162float(hx), v.y-__bfloat162float(hy));
            __nv_bfloat162 l23 = __floats2bfloat162_rn(v.z-__bfloat162float(hz), v.w-__bfloat162float(hw));
            *(__nv_bfloat162*)(sXh + pos*136 + lane*4)     = h01;
            *(__nv_bfloat162*)(sXh + pos*136 + lane*4 + 2) = h23;
            *(__nv_bfloat162*)(sXl + pos*136 + lane*4)     = l01;
            *(__nv_bfloat162*)(sXl + pos*136 + lane*4 + 2) = l23;
        }
    }

    float mrow[2][2];
    #pragma unroll
    for (int mf = 0; mf < 2; mf++) {
        int r = wm*32 + mf*16 + (lane >> 2);
        mrow[mf][0] = mask[pbase + r];
        mrow[mf][1] = mask[pbase + r + 8];
    }

    #pragma unroll 1
    for (int mat = 0; mat < 3; mat++) {
        const bool dual = (mat < 2);
        const int ia = (mat==0) ? 0 : (mat==1) ? 1 : 4;   // wl, wr, wog
        const int ib = (mat==0) ? 2 : 3;                  // wlg, wrg

        __syncthreads();                 // X ready (mat 0) / prior epilogue reads done
        copy_w128(g_wh[ia], g_wlo[ia], sWh, sWl, tid);
        __syncthreads();
        float accA[2][4][4] = {};
        gemm_tile3<4>(accA, sXh, sXl, sWh, sWl, lane, wm*32, wn*32);

        if (dual) {
            __syncthreads();             // WA reads done
            copy_w128(g_wh[ib], g_wlo[ib], sWh, sWl, tid);
            __syncthreads();
            float accB[2][4][4] = {};
            gemm_tile3<4>(accB, sXh, sXl, sWh, sWl, lane, wm*32, wn*32);

            __nv_bfloat16* s_stage = sWh;  // [128 h][68 pos], W dead after gemms
            __syncthreads();
            #pragma unroll
            for (int mf = 0; mf < 2; mf++)
                #pragma unroll
                for (int nf = 0; nf < 4; nf++) {
                    int row = wm*32 + mf*16 + (lane >> 2);
                    int col = wn*32 + nf*8 + (lane & 3)*2;
                    float g0 = 1.f/(1.f+__expf(-accB[mf][nf][0]));
                    float g1 = 1.f/(1.f+__expf(-accB[mf][nf][1]));
                    float g2 = 1.f/(1.f+__expf(-accB[mf][nf][2]));
                    float g3 = 1.f/(1.f+__expf(-accB[mf][nf][3]));
                    s_stage[ col   *68 + row  ] = __float2bfloat16(accA[mf][nf][0]*mrow[mf][0]*g0);
                    s_stage[(col+1)*68 + row  ] = __float2bfloat16(accA[mf][nf][1]*mrow[mf][0]*g1);
                    s_stage[ col   *68 + row+8] = __float2bfloat16(accA[mf][nf][2]*mrow[mf][1]*g2);
                    s_stage[(col+1)*68 + row+8] = __float2bfloat16(accA[mf][nf][3]*mrow[mf][1]*g3);
                }
            __syncthreads();
            __nv_bfloat16* gdst = (mat == 0) ? g_left : g_right;
            #pragma unroll
            for (int q = 0; q < 8; q++) {
                int idx = tid + 256*q, hh = idx >> 4, seg = (idx & 15) << 2;
                *(uint2*)(gdst + (size_t)hh*PP + pbase + seg) =
                    *(const uint2*)(s_stage + hh*68 + seg);
            }
        } else {
            #pragma unroll
            for (int mf = 0; mf < 2; mf++)
                #pragma unroll
                for (int nf = 0; nf < 4; nf++) {
                    int row = wm*32 + mf*16 + (lane >> 2);
                    int col = wn*32 + nf*8 + (lane & 3)*2;
                    float2 p0 = make_float2(1.f/(1.f+__expf(-accA[mf][nf][0])),
                                            1.f/(1.f+__expf(-accA[mf][nf][1])));
                    float2 p1 = make_float2(1.f/(1.f+__expf(-accA[mf][nf][2])),
                                            1.f/(1.f+__expf(-accA[mf][nf][3])));
                    *(float2*)(g_ogate + (pbase+row)*128 + col)   = p0;
                    *(float2*)(g_ogate + (pbase+row+8)*128 + col) = p1;
                }
        }
    }
}

// -------- Stage B: per-channel bf16 einsum, k-chunk 64, ldmatrix --------
#define SB_SMEM (4*128*72*2)   // 73728 B -> 2 CTAs/SM

__device__ __forceinline__ void cpa16(void* dst, const void* src) {
    unsigned u = (unsigned)__cvta_generic_to_shared(dst);
    asm volatile("cp.async.cg.shared.global [%0], [%1], 16;\n" :: "r"(u), "l"(src) : "memory");
}
__device__ __forceinline__ void sb_issue(const __nv_bfloat16* gA, const __nv_bfloat16* gB,
                                         __nv_bfloat16* sA, __nv_bfloat16* sB, int tid, int k0) {
    #pragma unroll
    for (int q = 0; q < 4; q++) {
        int idx = tid + 256*q, row = idx >> 3, seg = (idx & 7) << 3;
        cpa16(sA + row*72 + seg, gA + (size_t)row*NN + k0 + seg);
        cpa16(sB + row*72 + seg, gB + (size_t)row*NN + k0 + seg);
    }
    asm volatile("cp.async.commit_group;\n" ::: "memory");
}

__global__ __launch_bounds__(256, 2) void stage_b() {
    extern __shared__ __nv_bfloat16 smb[];
    __nv_bfloat16* sA = smb;              // [2 buf][128][72]
    __nv_bfloat16* sB = smb + 2*128*72;

    const int tid = threadIdx.x, lane = tid & 31, warp = tid >> 5;
    const int wm = warp & 1, wn = warp >> 1;
    const int d = blockIdx.y, ti = blockIdx.x / 6, tj = blockIdx.x % 6;
    const __nv_bfloat16* gA = g_left  + (size_t)d*PP + (size_t)(ti*128)*NN;
    const __nv_bfloat16* gB = g_right + (size_t)d*PP + (size_t)(tj*128)*NN;

    const int lr  = lane & 15, lkA = (lane >> 4) << 3;
    const int bn  = lane & 7, bks = ((lane >> 3) & 1) << 3;
    const int bnf = lane >> 4;

    float c[4][4][4] = {};
    sb_issue(gA, gB, sA, sB, tid, 0);

    #pragma unroll 1
    for (int kt = 0; kt < 12; kt++) {
        int buf = kt & 1;
        if (kt < 11) {
            sb_issue(gA, gB, sA + (buf^1)*9216, sB + (buf^1)*9216, tid, (kt+1)*64);
            asm volatile("cp.async.wait_group 1;\n" ::: "memory");
        } else {
            asm volatile("cp.async.wait_group 0;\n" ::: "memory");
        }
        __syncthreads();
        const __nv_bfloat16* Ab = sA + buf*9216;
        const __nv_bfloat16* Bb = sB + buf*9216;
        #pragma unroll
        for (int kk = 0; kk < 4; kk++) {
            uint32_t a[4][4], b[4][2];
            #pragma unroll
            for (int fm = 0; fm < 4; fm++)
                ldsm4(a[fm], Ab + (wm*64 + fm*16 + lr)*72 + kk*16 + lkA);
            #pragma unroll
            for (int nf = 0; nf < 4; nf += 2) {
                uint32_t t[4];
                ldsm4(t, Bb + (wn*32 + (nf + bnf)*8 + bn)*72 + kk*16 + bks);
                b[nf][0]=t[0]; b[nf][1]=t[1]; b[nf+1][0]=t[2]; b[nf+1][1]=t[3];
            }
            #pragma unroll
            for (int fm = 0; fm < 4; fm++)
                #pragma unroll
                for (int fn = 0; fn < 4; fn++) mma16816(c[fm][fn], a[fm], b[fn]);
        }
        __syncthreads();
    }

    __nv_bfloat16* gO = g_pair + (size_t)d*PP;
    #pragma unroll
    for (int fm = 0; fm < 4; fm++)
        #pragma unroll
        for (int fn = 0; fn < 4; fn++) {
            int r0 = ti*128 + wm*64 + fm*16 + (lane >> 2);
            int cc = tj*128 + wn*32 + fn*8 + (lane & 3)*2;
            *(__nv_bfloat162*)(gO + (size_t)r0*NN + cc) =
                __float22bfloat162_rn(make_float2(c[fm][fn][0], c[fm][fn][1]));
            *(__nv_bfloat162*)(gO + (size_t)(r0+8)*NN + cc) =
                __float22bfloat162_rn(make_float2(c[fm][fn][2], c[fm][fn][3]));
        }
}

// ------ Stage C (mma): LN over H + out_gate + final projection, M=64 ------
#define SC_SMEM (2*17408 + 2*34816)   // 102 KB -> 2 CTAs/SM

__global__ __launch_bounds__(256, 2) void stage_cmm(
    const float* __restrict__ onw, const float* __restrict__ onb,
    float* __restrict__ out)
{
    extern __shared__ __nv_bfloat16 smc[];
    __nv_bfloat16* s_vh = smc;            // [64 pos][136]
    __nv_bfloat16* s_vl = smc + 8704;
    __nv_bfloat16* s_wh = smc + 17408;    // [128 dout][136]
    __nv_bfloat16* s_wl = smc + 34816;
    __nv_bfloat16* s_t  = s_wh;           // [128 d][68] overlay, dead before w fill

    const int tid = threadIdx.x, lane = tid & 31, warp = tid >> 5;
    const int wm = warp & 1, wn = warp >> 1;
    const size_t p0 = (size_t)blockIdx.x * 64;

    #pragma unroll
    for (int q = 0; q < 8; q++) { // pair tile [128 d][64 pos]
        int idx = tid + 256*q, dd = idx >> 4, seg = (idx & 15) << 2;
        *(uint2*)(s_t + dd*68 + seg) = *(const uint2*)(g_pair + (size_t)dd*PP + p0 + seg);
    }
    __syncthreads();

    float lw[4], lb[4];
    #pragma unroll
    for (int q = 0; q < 4; q++) { lw[q] = onw[lane+32*q]; lb[q] = onb[lane+32*q]; }

    #pragma unroll 1
    for (int pp = 0; pp < 8; pp++) { // LN over d + gate, warp per position
        int pos = warp*8 + pp;
        float t[4];
        #pragma unroll
        for (int q = 0; q < 4; q++) t[q] = __bfloat162float(s_t[(lane+32*q)*68 + pos]);
        float s = t[0]+t[1]+t[2]+t[3];
        float sq = t[0]*t[0]+t[1]*t[1]+t[2]*t[2]+t[3]*t[3];
        #pragma unroll
        for (int o = 16; o; o >>= 1) {
            s  += __shfl_xor_sync(~0u, s,  o);
            sq += __shfl_xor_sync(~0u, sq, o);
        }
        float mu = s*(1.f/128.f), var = sq*(1.f/128.f) - mu*mu;
        float rstd = rsqrtf(var + 1e-5f);
        #pragma unroll
        for (int q = 0; q < 4; q++) {
            float v = (t[q]-mu)*rstd*lw[q] + lb[q];
            v *= g_ogate[(p0+pos)*128 + lane + 32*q];
            __nv_bfloat16 h = __float2bfloat16_rn(v);
            s_vh[pos*136 + lane + 32*q] = h;
            s_vl[pos*136 + lane + 32*q] = __float2bfloat16_rn(v - __bfloat162float(h));
        }
    }
    __syncthreads();  // LN reads of s_t done; safe to overwrite with w_out

    copy_w128(g_wh[5], g_wlo[5], s_wh, s_wl, tid);
    __syncthreads();

    float acc[2][4][4] = {};
    gemm_tile3<4>(acc, s_vh, s_vl, s_wh, s_wl, lane, wm*32, wn*32);

    #pragma unroll
    for (int mf = 0; mf < 2; mf++)
        #pragma unroll
        for (int nf = 0; nf < 4; nf++) {
            int row = wm*32 + mf*16 + (lane >> 2);
            int col = wn*32 + nf*8 + (lane & 3)*2;
            *(float2*)(out + (p0+row)*128 + col)   = make_float2(acc[mf][nf][0], acc[mf][nf][1]);
            *(float2*)(out + (p0+row+8)*128 + col) = make_float2(acc[mf][nf][2], acc[mf][nf][3]);
        }
}

// -----------------------------------------------------------------------------
extern "C" void kernel_launch(void* const* d_in, const int* in_sizes, int n_in,
                              void* d_out, int out_size) {
    (void)in_sizes; (void)n_in; (void)out_size;
    const float* x    = (const float*)d_in[0];
    const float* mask = (const float*)d_in[1];
    const float* nw   = (const float*)d_in[2];
    const float* nb   = (const float*)d_in[3];
    const float* wl   = (const float*)d_in[4];
    const float* wr   = (const float*)d_in[5];
    const float* wlg  = (const float*)d_in[6];
    const float* wrg  = (const float*)d_in[7];
    const float* wog  = (const float*)d_in[8];
    const float* onw  = (const float*)d_in[9];
    const float* onb  = (const float*)d_in[10];
    const float* wout = (const float*)d_in[11];
    float* out = (float*)d_out;

    cudaFuncSetAttribute(stage_a_fused, cudaFuncAttributeMaxDynamicSharedMemorySize, AM_SMEM);
    cudaFuncSetAttribute(stage_b,       cudaFuncAttributeMaxDynamicSharedMemorySize, SB_SMEM);
    cudaFuncSetAttribute(stage_cmm,     cudaFuncAttributeMaxDynamicSharedMemorySize, SC_SMEM);

    stage_wsplit<<<6, 256>>>(wl, wr, wlg, wrg, wog, wout);
    stage_a_fused<<<PP/64, 256, AM_SMEM>>>(x, mask, nw, nb);
    stage_b<<<dim3(36, 128), 256, SB_SMEM>>>();
    stage_cmm<<<PP/64, 256, SC_SMEM>>>(onw, onb, out);
}